// round 2
// baseline (speedup 1.0000x reference)
#include <cuda_runtime.h>
#include <cuda_bf16.h>
#include <math.h>

#define BB 4
#define CC_IN 128
#define HH 56
#define WW 56
#define HW 3136
#define MID 32
#define OG 512
#define COUT 128
#define GCN 4
#define K2 9
#define NPQ 28224
#define EPS 1e-5f

// ---------------- device scratch (no runtime allocation allowed) ----------------
__device__ float g_ke[BB * CC_IN * HW];      // relu(bn1(Wk x))
__device__ float g_v [BB * OG * HW];         // bnv(Wv x)
__device__ float g_hq[BB * MID * HW];        // W1q' x
__device__ float g_hk[BB * MID * HW];        // W1k' ke
__device__ float g_h [BB * MID * K2 * HW];   // relu(hq + hk_shift + bh), layout [b][m][p][hw]
__device__ float g_Wk [CC_IN * CC_IN];
__device__ float g_W1q[MID * CC_IN];
__device__ float g_W1k[MID * CC_IN];
__device__ float g_Wv [OG * CC_IN];
__device__ float g_bke[CC_IN];
__device__ float g_bh [MID];
__device__ float g_bv [OG];
__device__ float g_M  [BB * MID * MID];
__device__ float g_Sh [BB * MID];
__device__ float g_mu [BB * COUT];
__device__ float g_ri [BB * COUT];

__global__ void zero_kernel(float* p, int n) {
    int i = blockIdx.x * blockDim.x + threadIdx.x;
    if (i < n) p[i] = 0.f;
}

// Fold all inference-mode BN affines into weights / biases.
__global__ void fold_kernel(
    const float* __restrict__ Wk,
    const float* __restrict__ bn1g, const float* __restrict__ bn1b,
    const float* __restrict__ bn1m, const float* __restrict__ bn1v,
    const float* __restrict__ W1,  const float* __restrict__ b1,
    const float* __restrict__ bn2g, const float* __restrict__ bn2b,
    const float* __restrict__ bn2m, const float* __restrict__ bn2v,
    const float* __restrict__ Wv,
    const float* __restrict__ bnvg, const float* __restrict__ bnvb,
    const float* __restrict__ bnvm, const float* __restrict__ bnvv)
{
    int i = blockIdx.x * blockDim.x + threadIdx.x;
    if (i < 16384) {                               // Wk' = s1[d]*Wk[d,c]
        int d = i >> 7;
        float s = bn1g[d] * rsqrtf(bn1v[d] + EPS);
        g_Wk[i] = Wk[i] * s;
    } else if (i < 20480) {                        // W1q' = s2[m]*W1[m, 0:128]
        int j = i - 16384; int m = j >> 7; int c = j & 127;
        float s = bn2g[m] * rsqrtf(bn2v[m] + EPS);
        g_W1q[j] = W1[m * 256 + c] * s;
    } else if (i < 24576) {                        // W1k' = s2[m]*W1[m, 128:256]
        int j = i - 20480; int m = j >> 7; int c = j & 127;
        float s = bn2g[m] * rsqrtf(bn2v[m] + EPS);
        g_W1k[j] = W1[m * 256 + 128 + c] * s;
    } else if (i < 90112) {                        // Wv' = sv[o]*Wv[o,c]
        int j = i - 24576; int o = j >> 7;
        float s = bnvg[o] * rsqrtf(bnvv[o] + EPS);
        g_Wv[j] = Wv[j] * s;
    } else if (i < 90240) {                        // bke
        int d = i - 90112;
        float s = bn1g[d] * rsqrtf(bn1v[d] + EPS);
        g_bke[d] = bn1b[d] - bn1m[d] * s;
    } else if (i < 90272) {                        // bh = s2*b1 + t2
        int m = i - 90240;
        float s = bn2g[m] * rsqrtf(bn2v[m] + EPS);
        g_bh[m] = s * b1[m] + bn2b[m] - bn2m[m] * s;
    } else if (i < 90784) {                        // bv
        int o = i - 90272;
        float s = bnvg[o] * rsqrtf(bnvv[o] + EPS);
        g_bv[o] = bnvb[o] - bnvm[o] * s;
    }
}

// ---------------- pointwise-conv GEMM: Y[b,d,hw] = act(W[d,:]·X[b,:,hw] + bias) ----------------
// grid (HW/64, Dtot/DTILE, B); 256 threads; C chunked by 64.
template<int DTILE, bool RELU>
__global__ void pw_conv_kernel(const float* __restrict__ X, const float* __restrict__ Wm,
                               const float* __restrict__ bias, float* __restrict__ Y,
                               int Dtot)
{
    constexpr int PX = 64;
    constexpr int CCH = 64;
    constexpr int DN = DTILE / 16;
    __shared__ float sX[CCH][PX];
    __shared__ float sW[CCH][DTILE + 1];
    const int b   = blockIdx.z;
    const int hw0 = blockIdx.x * PX;
    const int d0  = blockIdx.y * DTILE;
    const int tid = threadIdx.x;
    const int tx  = tid & 15;      // pixel lane: handles px = tx, tx+16, tx+32, tx+48
    const int ty  = tid >> 4;      // output-channel group: 16 groups of DN
    float acc[DN][4];
    #pragma unroll
    for (int j = 0; j < DN; j++)
        #pragma unroll
        for (int i = 0; i < 4; i++) acc[j][i] = 0.f;
    const float* Xb = X + (size_t)b * CC_IN * HW;
    for (int cc = 0; cc < CC_IN; cc += CCH) {
        for (int k = tid; k < CCH * PX; k += 256) {
            int c = k >> 6, px = k & 63;
            sX[c][px] = Xb[(size_t)(cc + c) * HW + hw0 + px];
        }
        for (int k = tid; k < DTILE * CCH; k += 256) {
            int d = k >> 6, c = k & 63;
            sW[c][d] = Wm[(size_t)(d0 + d) * CC_IN + cc + c];
        }
        __syncthreads();
        #pragma unroll 8
        for (int c = 0; c < CCH; c++) {
            float xv[4];
            #pragma unroll
            for (int i = 0; i < 4; i++) xv[i] = sX[c][tx + 16 * i];
            #pragma unroll
            for (int j = 0; j < DN; j++) {
                float wv = sW[c][ty * DN + j];
                #pragma unroll
                for (int i = 0; i < 4; i++) acc[j][i] = fmaf(wv, xv[i], acc[j][i]);
            }
        }
        __syncthreads();
    }
    #pragma unroll
    for (int j = 0; j < DN; j++) {
        int d = d0 + ty * DN + j;
        float bsv = bias ? bias[d] : 0.f;
        #pragma unroll
        for (int i = 0; i < 4; i++) {
            float r = acc[j][i] + bsv;
            if (RELU) r = fmaxf(r, 0.f);
            Y[((size_t)b * Dtot + d) * HW + hw0 + tx + 16 * i] = r;
        }
    }
}

// ---------------- h materialization with 3x3 unfold (zero pad on hk) ----------------
__global__ void hmat_kernel(const float* __restrict__ hq, const float* __restrict__ hk,
                            float* __restrict__ h)
{
    int i = blockIdx.x * blockDim.x + threadIdx.x;
    if (i >= BB * MID * K2 * HW) return;
    int hw = i % HW;
    int t  = i / HW;
    int p  = t % K2;
    int t2 = t / K2;
    int m  = t2 % MID;
    int b  = t2 / MID;
    int y = hw / WW, x = hw % WW;
    int di = p / 3 - 1, dj = p % 3 - 1;
    int ny = y + di, nx = x + dj;
    float hkv = 0.f;
    if (ny >= 0 && ny < HH && nx >= 0 && nx < WW)
        hkv = hk[((size_t)b * MID + m) * HW + ny * WW + nx];
    float val = hq[((size_t)b * MID + m) * HW + hw] + hkv + g_bh[m];
    h[i] = fmaxf(val, 0.f);
}

// ---------------- Sh[b,m] = sum over (p,hw) of h ----------------
__global__ void shsum_kernel(const float* __restrict__ h, float* __restrict__ Sh)
{
    int m = blockIdx.x, b = blockIdx.y;
    const float* p = h + (size_t)(b * MID + m) * NPQ;
    float s = 0.f;
    for (int k = threadIdx.x; k < NPQ; k += 256) s += p[k];
    __shared__ float red[256];
    red[threadIdx.x] = s;
    __syncthreads();
    for (int off = 128; off > 0; off >>= 1) {
        if (threadIdx.x < off) red[threadIdx.x] += red[threadIdx.x + off];
        __syncthreads();
    }
    if (threadIdx.x == 0) Sh[b * MID + m] = red[0];
}

// ---------------- Gram: M[b,i,j] += sum_q h[b,i,q] h[b,j,q] (q over p*hw flattened) ----------------
// grid (84, B), 256 threads; q-chunk 336 (84*336 = 28224 exactly).
__global__ void gram_kernel(const float* __restrict__ h, float* __restrict__ M)
{
    __shared__ float sh[32 * 337];
    int b  = blockIdx.y;
    int q0 = blockIdx.x * 336;
    const float* hb = h + (size_t)b * MID * NPQ;
    for (int k = threadIdx.x; k < 32 * 336; k += 256) {
        int m = k / 336, q = k % 336;
        sh[m * 337 + q] = hb[(size_t)m * NPQ + q0 + q];
    }
    __syncthreads();
    int grp = threadIdx.x >> 6;   // 4 groups split the 336 q's
    int r   = threadIdx.x & 63;
    int it  = r & 7, jt = r >> 3; // 8x8 grid of 4x4 micro-tiles
    float acc[4][4];
    #pragma unroll
    for (int a = 0; a < 4; a++)
        #pragma unroll
        for (int c = 0; c < 4; c++) acc[a][c] = 0.f;
    int qlo = grp * 84, qhi = qlo + 84;
    for (int q = qlo; q < qhi; q++) {
        float hi[4], hj[4];
        #pragma unroll
        for (int a = 0; a < 4; a++) hi[a] = sh[(it * 4 + a) * 337 + q];
        #pragma unroll
        for (int c = 0; c < 4; c++) hj[c] = sh[(jt * 4 + c) * 337 + q];
        #pragma unroll
        for (int a = 0; a < 4; a++)
            #pragma unroll
            for (int c = 0; c < 4; c++) acc[a][c] = fmaf(hi[a], hj[c], acc[a][c]);
    }
    #pragma unroll
    for (int a = 0; a < 4; a++)
        #pragma unroll
        for (int c = 0; c < 4; c++)
            atomicAdd(&M[b * 1024 + (it * 4 + a) * 32 + (jt * 4 + c)], acc[a][c]);
}

// ---------------- GroupNorm stats via quadratic forms ----------------
__global__ void stats_kernel(const float* __restrict__ W2, const float* __restrict__ b2,
                             const float* __restrict__ M, const float* __restrict__ Sh,
                             float* __restrict__ mu, float* __restrict__ rinv)
{
    int b = blockIdx.x, o = threadIdx.x;  // 128 threads, one per cout
    __shared__ float sM[1024], sSh[32];
    for (int k = o; k < 1024; k += 128) sM[k] = M[b * 1024 + k];
    if (o < 32) sSh[o] = Sh[b * 32 + o];
    __syncthreads();
    float S1 = 0.f, S2 = 0.f;
    const float NPf = (float)NPQ;
    for (int g = 0; g < GCN; g++) {
        int og = o * GCN + g;
        float w[32];
        #pragma unroll
        for (int m = 0; m < 32; m++) w[m] = W2[og * 32 + m];
        float d1 = 0.f;
        #pragma unroll
        for (int m = 0; m < 32; m++) d1 = fmaf(w[m], sSh[m], d1);
        float q = 0.f;
        for (int i2 = 0; i2 < 32; i2++) {
            float ti = 0.f;
            #pragma unroll
            for (int j = 0; j < 32; j++) ti = fmaf(sM[i2 * 32 + j], w[j], ti);
            q = fmaf(w[i2], ti, q);
        }
        float bbv = b2[og];
        S1 += d1 + bbv * NPf;
        S2 += q + 2.f * bbv * d1 + bbv * bbv * NPf;
    }
    const float N = (float)(GCN * NPQ);
    float m_ = S1 / N;
    float var = S2 / N - m_ * m_;
    mu[b * COUT + o]   = m_;
    rinv[b * COUT + o] = rsqrtf(var + EPS);
}

// ---------------- main fused kernel: a-GEMM + GN affine + a*V reduction ----------------
// grid (7, 14, B): 8x4 spatial tile; all 128 cout per block; 256 threads.
// dyn smem = (9216 + 7936 + 4224) * 4 = 85504 B.
__global__ void __launch_bounds__(256, 2) main_kernel(
    const float* __restrict__ h, const float* __restrict__ v,
    const float* __restrict__ W2, const float* __restrict__ b2,
    const float* __restrict__ gng, const float* __restrict__ gnb,
    const float* __restrict__ mu, const float* __restrict__ rinv,
    float* __restrict__ out)
{
    extern __shared__ float smem[];
    float* sH = smem;             // [m*9+p][32 px]        = 9216 floats
    float* sV = sH + 9216;        // [128 o][62 (10x6 pad)] = 7936 floats
    float* sW = sV + 7936;        // [128 o][33]            = 4224 floats
    const int b   = blockIdx.z;
    const int x0  = blockIdx.x * 8;
    const int y0  = blockIdx.y * 4;
    const int tid = threadIdx.x;
    const int tpx = tid & 7;      // x within tile
    const int to  = tid >> 3;     // 0..31, each handles 4 couts

    // Stage h for this tile: [MID*K2][32]
    const float* hb = h + (size_t)b * MID * K2 * HW;
    for (int k = tid; k < 9216; k += 256) {
        int mp = k >> 5;          // m*9+p
        int px = k & 31;
        int ly = px >> 3, lx = px & 7;
        sH[mp * 32 + px] = hb[(size_t)mp * HW + (y0 + ly) * WW + (x0 + lx)];
    }

    float acc[4][4];
    #pragma unroll
    for (int oo = 0; oo < 4; oo++)
        #pragma unroll
        for (int r = 0; r < 4; r++) acc[oo][r] = 0.f;

    const float* vb = v + (size_t)b * OG * HW;
    for (int g = 0; g < GCN; g++) {
        __syncthreads();
        // V tile with halo: 10x6 per (o), zero-padded at image borders
        for (int k = tid; k < 128 * 60; k += 256) {
            int o = k / 60, s = k % 60;
            int yy = s / 10, xx = s % 10;
            int gy = y0 - 1 + yy, gx = x0 - 1 + xx;
            float val = 0.f;
            if (gy >= 0 && gy < HH && gx >= 0 && gx < WW)
                val = vb[(size_t)(o * GCN + g) * HW + gy * WW + gx];
            sV[o * 62 + s] = val;
        }
        // W2 rows for this g
        for (int k = tid; k < 128 * 32; k += 256) {
            int o = k >> 5, m = k & 31;
            sW[o * 33 + m] = W2[(o * GCN + g) * 32 + m];
        }
        __syncthreads();

        float c1r[4], c0r[4];
        #pragma unroll
        for (int oo = 0; oo < 4; oo++) {
            int o = to * 4 + oo;
            int og = o * GCN + g;
            float c1 = rinv[b * COUT + o] * gng[og];
            c1r[oo] = c1;
            c0r[oo] = c1 * b2[og] + gnb[og] - mu[b * COUT + o] * c1;
        }

        for (int p = 0; p < K2; p++) {
            float aacc[4][4];
            #pragma unroll
            for (int oo = 0; oo < 4; oo++)
                #pragma unroll
                for (int r = 0; r < 4; r++) aacc[oo][r] = 0.f;
            #pragma unroll
            for (int m = 0; m < 32; m++) {
                float hv[4];
                #pragma unroll
                for (int r = 0; r < 4; r++) hv[r] = sH[(m * 9 + p) * 32 + tpx + 8 * r];
                #pragma unroll
                for (int oo = 0; oo < 4; oo++) {
                    float w = sW[(to * 4 + oo) * 33 + m];
                    #pragma unroll
                    for (int r = 0; r < 4; r++) aacc[oo][r] = fmaf(w, hv[r], aacc[oo][r]);
                }
            }
            int di = p / 3 - 1, dj = p % 3 - 1;
            #pragma unroll
            for (int oo = 0; oo < 4; oo++) {
                #pragma unroll
                for (int r = 0; r < 4; r++) {
                    float Vv = sV[(to * 4 + oo) * 62 + (r + 1 + di) * 10 + (tpx + 1 + dj)];
                    float t = fmaf(c1r[oo], aacc[oo][r], c0r[oo]);
                    acc[oo][r] = fmaf(t, Vv, acc[oo][r]);
                }
            }
        }
    }
    #pragma unroll
    for (int oo = 0; oo < 4; oo++)
        #pragma unroll
        for (int r = 0; r < 4; r++)
            out[((size_t)b * COUT + to * 4 + oo) * HW + (y0 + r) * WW + x0 + tpx] = acc[oo][r];
}

// ---------------- launch ----------------
extern "C" void kernel_launch(void* const* d_in, const int* in_sizes, int n_in,
                              void* d_out, int out_size)
{
    const float* x     = (const float*)d_in[0];
    const float* Wk    = (const float*)d_in[1];
    const float* bn1g  = (const float*)d_in[2];
    const float* bn1b  = (const float*)d_in[3];
    const float* bn1m  = (const float*)d_in[4];
    const float* bn1v  = (const float*)d_in[5];
    const float* W1    = (const float*)d_in[6];
    const float* b1    = (const float*)d_in[7];
    const float* bn2g  = (const float*)d_in[8];
    const float* bn2b  = (const float*)d_in[9];
    const float* bn2m  = (const float*)d_in[10];
    const float* bn2v  = (const float*)d_in[11];
    const float* W2    = (const float*)d_in[12];
    const float* b2    = (const float*)d_in[13];
    const float* gng   = (const float*)d_in[14];
    const float* gnb   = (const float*)d_in[15];
    const float* Wv    = (const float*)d_in[16];
    const float* bnvg  = (const float*)d_in[17];
    const float* bnvb  = (const float*)d_in[18];
    const float* bnvm  = (const float*)d_in[19];
    const float* bnvv  = (const float*)d_in[20];
    float* out = (float*)d_out;

    float *ke, *vv, *hq, *hk, *hh, *pM, *pSh, *pmu, *pri;
    float *pWk, *pW1q, *pW1k, *pWv, *pbke, *pbv;
    cudaGetSymbolAddress((void**)&ke,   g_ke);
    cudaGetSymbolAddress((void**)&vv,   g_v);
    cudaGetSymbolAddress((void**)&hq,   g_hq);
    cudaGetSymbolAddress((void**)&hk,   g_hk);
    cudaGetSymbolAddress((void**)&hh,   g_h);
    cudaGetSymbolAddress((void**)&pM,   g_M);
    cudaGetSymbolAddress((void**)&pSh,  g_Sh);
    cudaGetSymbolAddress((void**)&pmu,  g_mu);
    cudaGetSymbolAddress((void**)&pri,  g_ri);
    cudaGetSymbolAddress((void**)&pWk,  g_Wk);
    cudaGetSymbolAddress((void**)&pW1q, g_W1q);
    cudaGetSymbolAddress((void**)&pW1k, g_W1k);
    cudaGetSymbolAddress((void**)&pWv,  g_Wv);
    cudaGetSymbolAddress((void**)&pbke, g_bke);
    cudaGetSymbolAddress((void**)&pbv,  g_bv);

    static bool attr_set = false;
    if (!attr_set) {
        cudaFuncSetAttribute(main_kernel, cudaFuncAttributeMaxDynamicSharedMemorySize, 85504);
        attr_set = true;
    }

    zero_kernel<<<16, 256>>>(pM, BB * MID * MID);
    fold_kernel<<<(90784 + 255) / 256, 256>>>(Wk, bn1g, bn1b, bn1m, bn1v,
                                              W1, b1, bn2g, bn2b, bn2m, bn2v,
                                              Wv, bnvg, bnvb, bnvm, bnvv);
    pw_conv_kernel<64, true ><<<dim3(49, 2, BB), 256>>>(x,  pWk,  pbke,    ke, CC_IN);
    pw_conv_kernel<64, false><<<dim3(49, 8, BB), 256>>>(x,  pWv,  pbv,     vv, OG);
    pw_conv_kernel<32, false><<<dim3(49, 1, BB), 256>>>(x,  pW1q, nullptr, hq, MID);
    pw_conv_kernel<32, false><<<dim3(49, 1, BB), 256>>>(ke, pW1k, nullptr, hk, MID);
    hmat_kernel<<<(BB * MID * K2 * HW + 255) / 256, 256>>>(hq, hk, hh);
    shsum_kernel<<<dim3(MID, BB), 256>>>(hh, pSh);
    gram_kernel<<<dim3(84, BB), 256>>>(hh, pM);
    stats_kernel<<<BB, 128>>>(W2, b2, pM, pSh, pmu, pri);
    main_kernel<<<dim3(7, 14, BB), 256, 85504>>>(hh, vv, W2, b2, gng, gnb, pmu, pri, out);
}

// round 3
// speedup vs baseline: 1.3301x; 1.3301x over previous
#include <cuda_runtime.h>
#include <cuda_bf16.h>
#include <math.h>

#define BB 4
#define CC_IN 128
#define HH 56
#define WW 56
#define HW 3136
#define MID 32
#define OG 512
#define COUT 128
#define GCN 4
#define K2 9
#define NPQ 28224
#define EPS 1e-5f

// ---------------- device scratch ----------------
__device__ float g_ke[BB * CC_IN * HW];      // relu(bn1(Wk x))
__device__ float g_v [BB * OG * HW];         // bnv(Wv x)
__device__ float g_hq[BB * MID * HW];        // W1q' x
__device__ float g_hk[BB * MID * HW];        // W1k' ke
__device__ float g_Wkt [CC_IN * CC_IN];      // transposed [c][d]
__device__ float g_W1qt[CC_IN * MID];        // [c][m]
__device__ float g_W1kt[CC_IN * MID];        // [c][m]
__device__ float g_Wvt [CC_IN * OG];         // [c][o]
__device__ float g_W2t [GCN * MID * COUT];   // [g][m][o]
__device__ float g_bke[CC_IN];
__device__ float g_bh [MID];
__device__ float g_bv [OG];
__device__ float g_M  [BB * MID * MID];
__device__ float g_Sh [BB * MID];
__device__ float g_mu [BB * COUT];
__device__ float g_ri [BB * COUT];

__global__ void zero_kernel(float* p, int n) {
    int i = blockIdx.x * blockDim.x + threadIdx.x;
    if (i < n) p[i] = 0.f;
}

// Fold BN affines into weights; write all weights TRANSPOSED for coalesced staging.
__global__ void fold_kernel(
    const float* __restrict__ Wk,
    const float* __restrict__ bn1g, const float* __restrict__ bn1b,
    const float* __restrict__ bn1m, const float* __restrict__ bn1v,
    const float* __restrict__ W1,  const float* __restrict__ b1,
    const float* __restrict__ bn2g, const float* __restrict__ bn2b,
    const float* __restrict__ bn2m, const float* __restrict__ bn2v,
    const float* __restrict__ W2,
    const float* __restrict__ Wv,
    const float* __restrict__ bnvg, const float* __restrict__ bnvb,
    const float* __restrict__ bnvm, const float* __restrict__ bnvv)
{
    int i = blockIdx.x * blockDim.x + threadIdx.x;
    if (i < 16384) {                          // Wkt[c][d] = s1[d]*Wk[d][c]
        int d = i >> 7, c = i & 127;
        float s = bn1g[d] * rsqrtf(bn1v[d] + EPS);
        g_Wkt[c * 128 + d] = Wk[d * 128 + c] * s;
    } else if (i < 20480) {                   // W1qt[c][m] = s2[m]*W1[m][c]
        int j = i - 16384; int m = j >> 7, c = j & 127;
        float s = bn2g[m] * rsqrtf(bn2v[m] + EPS);
        g_W1qt[c * MID + m] = W1[m * 256 + c] * s;
    } else if (i < 24576) {                   // W1kt[c][m] = s2[m]*W1[m][128+c]
        int j = i - 20480; int m = j >> 7, c = j & 127;
        float s = bn2g[m] * rsqrtf(bn2v[m] + EPS);
        g_W1kt[c * MID + m] = W1[m * 256 + 128 + c] * s;
    } else if (i < 90112) {                   // Wvt[c][o] = sv[o]*Wv[o][c]
        int j = i - 24576; int o = j >> 7, c = j & 127;
        float s = bnvg[o] * rsqrtf(bnvv[o] + EPS);
        g_Wvt[c * OG + o] = Wv[o * 128 + c] * s;
    } else if (i < 106496) {                  // W2t[g][m][o] = W2[o*4+g][m]
        int j = i - 90112; int o = j & 127, t = j >> 7;
        int g = t >> 5, m = t & 31;
        g_W2t[(g * MID + m) * COUT + o] = W2[(o * GCN + g) * MID + m];
    } else if (i < 106624) {                  // bke
        int d = i - 106496;
        float s = bn1g[d] * rsqrtf(bn1v[d] + EPS);
        g_bke[d] = bn1b[d] - bn1m[d] * s;
    } else if (i < 106656) {                  // bh = s2*b1 + t2
        int m = i - 106624;
        float s = bn2g[m] * rsqrtf(bn2v[m] + EPS);
        g_bh[m] = s * b1[m] + bn2b[m] - bn2m[m] * s;
    } else if (i < 107168) {                  // bv
        int o = i - 106656;
        float s = bnvg[o] * rsqrtf(bnvv[o] + EPS);
        g_bv[o] = bnvb[o] - bnvm[o] * s;
    }
}

// ---------------- pointwise-conv GEMM, vectorized (LDS.128 on both operands) ----------------
// Wt is TRANSPOSED [c][Dtot]. grid (HW/64, Dtot/DTILE, B), 256 threads.
template<int DTILE, bool RELU>
__global__ void pw_conv_kernel(const float* __restrict__ X, const float* __restrict__ Wt,
                               const float* __restrict__ bias, float* __restrict__ Y,
                               int Dtot)
{
    constexpr int PX = 64;
    constexpr int CCH = 64;
    constexpr int DN = DTILE / 16;
    __shared__ float sX[CCH * PX];
    __shared__ float sW[CCH * DTILE];
    const int b   = blockIdx.z;
    const int hw0 = blockIdx.x * PX;
    const int d0  = blockIdx.y * DTILE;
    const int tid = threadIdx.x;
    const int tx  = tid & 15;   // 4 contiguous px: 4tx..4tx+3
    const int ty  = tid >> 4;   // d group
    float acc[DN][4];
    #pragma unroll
    for (int j = 0; j < DN; j++)
        #pragma unroll
        for (int i = 0; i < 4; i++) acc[j][i] = 0.f;
    const float* Xb = X + (size_t)b * CC_IN * HW;
    for (int cc = 0; cc < CC_IN; cc += CCH) {
        for (int k = tid; k < CCH * PX; k += 256) {
            int c = k >> 6, px = k & 63;
            sX[k] = Xb[(size_t)(cc + c) * HW + hw0 + px];
        }
        for (int k = tid; k < CCH * DTILE; k += 256) {
            int c = k / DTILE, d = k % DTILE;
            sW[k] = Wt[(size_t)(cc + c) * Dtot + d0 + d];
        }
        __syncthreads();
        #pragma unroll 8
        for (int c = 0; c < CCH; c++) {
            float4 xv = *(const float4*)&sX[c * 64 + 4 * tx];
            #pragma unroll
            for (int jq = 0; jq < DN / 4 + (DN < 4 ? 1 : 0); jq++) { }
            if (DN == 4) {
                float4 w = *(const float4*)&sW[c * DTILE + ty * 4];
                acc[0][0] = fmaf(w.x, xv.x, acc[0][0]); acc[0][1] = fmaf(w.x, xv.y, acc[0][1]);
                acc[0][2] = fmaf(w.x, xv.z, acc[0][2]); acc[0][3] = fmaf(w.x, xv.w, acc[0][3]);
                acc[1][0] = fmaf(w.y, xv.x, acc[1][0]); acc[1][1] = fmaf(w.y, xv.y, acc[1][1]);
                acc[1][2] = fmaf(w.y, xv.z, acc[1][2]); acc[1][3] = fmaf(w.y, xv.w, acc[1][3]);
                acc[2][0] = fmaf(w.z, xv.x, acc[2][0]); acc[2][1] = fmaf(w.z, xv.y, acc[2][1]);
                acc[2][2] = fmaf(w.z, xv.z, acc[2][2]); acc[2][3] = fmaf(w.z, xv.w, acc[2][3]);
                acc[3][0] = fmaf(w.w, xv.x, acc[3][0]); acc[3][1] = fmaf(w.w, xv.y, acc[3][1]);
                acc[3][2] = fmaf(w.w, xv.z, acc[3][2]); acc[3][3] = fmaf(w.w, xv.w, acc[3][3]);
            } else { // DN == 2
                float2 w = *(const float2*)&sW[c * DTILE + ty * 2];
                acc[0][0] = fmaf(w.x, xv.x, acc[0][0]); acc[0][1] = fmaf(w.x, xv.y, acc[0][1]);
                acc[0][2] = fmaf(w.x, xv.z, acc[0][2]); acc[0][3] = fmaf(w.x, xv.w, acc[0][3]);
                acc[1][0] = fmaf(w.y, xv.x, acc[1][0]); acc[1][1] = fmaf(w.y, xv.y, acc[1][1]);
                acc[1][2] = fmaf(w.y, xv.z, acc[1][2]); acc[1][3] = fmaf(w.y, xv.w, acc[1][3]);
            }
        }
        __syncthreads();
    }
    #pragma unroll
    for (int j = 0; j < DN; j++) {
        int d = d0 + ty * DN + j;
        float bsv = bias ? bias[d] : 0.f;
        float4 r;
        r.x = acc[j][0] + bsv; r.y = acc[j][1] + bsv;
        r.z = acc[j][2] + bsv; r.w = acc[j][3] + bsv;
        if (RELU) {
            r.x = fmaxf(r.x, 0.f); r.y = fmaxf(r.y, 0.f);
            r.z = fmaxf(r.z, 0.f); r.w = fmaxf(r.w, 0.f);
        }
        *(float4*)&Y[((size_t)b * Dtot + d) * HW + hw0 + 4 * tx] = r;
    }
}

// ---------------- fused GroupNorm stats: Sh + Gram M directly from hq/hk ----------------
// h[m,p,px] = relu(hq[m,px] + hk[m, px shifted by p] + bh[m]), computed on the fly.
// grid (28, B): each block = 2 image rows.
__global__ void fused_stats_kernel(const float* __restrict__ hq, const float* __restrict__ hk,
                                   const float* __restrict__ bh,
                                   float* __restrict__ M, float* __restrict__ Sh)
{
    __shared__ float s_hq[32 * 112];   // [m][r*56+x], r in 0..1
    __shared__ float s_hk[32 * 224];   // [m][rr*56+x], rr in 0..3 = rows y0-1..y0+2 (0-pad)
    __shared__ float sBH[32];
    __shared__ float sSh[32];
    __shared__ float sM[1024];
    const int b  = blockIdx.y;
    const int y0 = blockIdx.x * 2;
    const int tid = threadIdx.x;
    if (tid < 32) { sBH[tid] = bh[tid]; sSh[tid] = 0.f; }
    for (int k = tid; k < 1024; k += 256) sM[k] = 0.f;
    for (int k = tid; k < 32 * 112; k += 256) {
        int m = k / 112, s = k % 112, r = s / 56, x = s % 56;
        s_hq[k] = hq[((size_t)b * MID + m) * HW + (y0 + r) * WW + x];
    }
    for (int k = tid; k < 32 * 224; k += 256) {
        int m = k / 224, s = k % 224, rr = s / 56, x = s % 56;
        int yy = y0 - 1 + rr;
        s_hk[k] = (yy >= 0 && yy < HH) ? hk[((size_t)b * MID + m) * HW + yy * WW + x] : 0.f;
    }
    __syncthreads();
    // Sh: thread (m = tid&31, chunk = tid>>5) sums 14 px * 9 p
    {
        int m = tid & 31, ch = tid >> 5;
        float s = 0.f;
        float base = sBH[m];
        for (int px = ch * 14; px < ch * 14 + 14; px++) {
            int r = px / 56, x = px % 56;
            float hqv = s_hq[m * 112 + px] + base;
            #pragma unroll
            for (int p = 0; p < 9; p++) {
                int di = p / 3, dj = p % 3;
                int xx = x + dj - 1;
                float hkv = (xx >= 0 && xx < WW) ? s_hk[m * 224 + (r + di) * 56 + xx] : 0.f;
                s += fmaxf(hqv + hkv, 0.f);
            }
        }
        atomicAdd(&sSh[m], s);
    }
    // Gram M: thread combo (it,jt) in 8x8, 4 px-groups of 28
    {
        int combo = tid & 63;
        int it = combo & 7, jt = combo >> 3;
        int pg = tid >> 6;
        float accM[4][4];
        #pragma unroll
        for (int a = 0; a < 4; a++)
            #pragma unroll
            for (int c = 0; c < 4; c++) accM[a][c] = 0.f;
        for (int px = pg * 28; px < pg * 28 + 28; px++) {
            int r = px / 56, x = px % 56;
            for (int p = 0; p < 9; p++) {
                int di = p / 3, dj = p % 3;
                int xx = x + dj - 1;
                bool in = (xx >= 0 && xx < WW);
                float hi[4], hj[4];
                #pragma unroll
                for (int a = 0; a < 4; a++) {
                    int m = it * 4 + a;
                    float hkv = in ? s_hk[m * 224 + (r + di) * 56 + xx] : 0.f;
                    hi[a] = fmaxf(s_hq[m * 112 + px] + hkv + sBH[m], 0.f);
                }
                #pragma unroll
                for (int c = 0; c < 4; c++) {
                    int m = jt * 4 + c;
                    float hkv = in ? s_hk[m * 224 + (r + di) * 56 + xx] : 0.f;
                    hj[c] = fmaxf(s_hq[m * 112 + px] + hkv + sBH[m], 0.f);
                }
                #pragma unroll
                for (int a = 0; a < 4; a++)
                    #pragma unroll
                    for (int c = 0; c < 4; c++) accM[a][c] = fmaf(hi[a], hj[c], accM[a][c]);
            }
        }
        #pragma unroll
        for (int a = 0; a < 4; a++)
            #pragma unroll
            for (int c = 0; c < 4; c++)
                atomicAdd(&sM[(it * 4 + a) * 32 + jt * 4 + c], accM[a][c]);
    }
    __syncthreads();
    if (tid < 32) atomicAdd(&Sh[b * 32 + tid], sSh[tid]);
    for (int k = tid; k < 1024; k += 256) atomicAdd(&M[b * 1024 + k], sM[k]);
}

// ---------------- GroupNorm stats via quadratic forms ----------------
__global__ void stats_kernel(const float* __restrict__ W2, const float* __restrict__ b2,
                             const float* __restrict__ M, const float* __restrict__ Sh,
                             float* __restrict__ mu, float* __restrict__ rinv)
{
    int b = blockIdx.x, o = threadIdx.x;  // 128 threads
    __shared__ float sM[1024], sSh[32];
    for (int k = o; k < 1024; k += 128) sM[k] = M[b * 1024 + k];
    if (o < 32) sSh[o] = Sh[b * 32 + o];
    __syncthreads();
    float S1 = 0.f, S2 = 0.f;
    const float NPf = (float)NPQ;
    for (int g = 0; g < GCN; g++) {
        int og = o * GCN + g;
        float w[32];
        #pragma unroll
        for (int m = 0; m < 32; m++) w[m] = W2[og * 32 + m];
        float d1 = 0.f;
        #pragma unroll
        for (int m = 0; m < 32; m++) d1 = fmaf(w[m], sSh[m], d1);
        float q = 0.f;
        for (int i2 = 0; i2 < 32; i2++) {
            float ti = 0.f;
            #pragma unroll
            for (int j = 0; j < 32; j++) ti = fmaf(sM[i2 * 32 + j], w[j], ti);
            q = fmaf(w[i2], ti, q);
        }
        float bbv = b2[og];
        S1 += d1 + bbv * NPf;
        S2 += q + 2.f * bbv * d1 + bbv * bbv * NPf;
    }
    const float N = (float)(GCN * NPQ);
    float m_ = S1 / N;
    float var = S2 / N - m_ * m_;
    mu[b * COUT + o]   = m_;
    rinv[b * COUT + o] = rsqrtf(var + EPS);
}

// ---------------- main fused kernel ----------------
// grid (7, 14, B): 8x4 px tile, all 128 couts. 256 threads.
// thread: tq = tid&7 owns 4 contiguous px (4tq..4tq+3); to = tid>>3 owns 4 contiguous o.
// smem: sH [p][m][32px] 9216 | sV [o][62] 7936 | sWt [m][132] 4224 | sBH 32 -> 85632 B
__global__ void __launch_bounds__(256, 2) main_kernel(
    const float* __restrict__ hq, const float* __restrict__ hk,
    const float* __restrict__ v,
    const float* __restrict__ W2t, const float* __restrict__ b2,
    const float* __restrict__ gng, const float* __restrict__ gnb,
    const float* __restrict__ mu, const float* __restrict__ rinv,
    const float* __restrict__ bh, float* __restrict__ out)
{
    extern __shared__ float smem[];
    float* sH  = smem;                    // 9216
    float* sV  = smem + 9216;             // 7936
    float* sWt = smem + 9216 + 7936;      // 4224
    float* sBH = smem + 9216 + 7936 + 4224; // 32
    float* s_hq = sV;                     // staging overlay: 1024
    float* s_hk = sV + 1024;              // staging overlay: 1920
    const int b   = blockIdx.z;
    const int x0  = blockIdx.x * 8;
    const int y0  = blockIdx.y * 4;
    const int tid = threadIdx.x;
    const int tq  = tid & 7;
    const int to  = tid >> 3;

    if (tid < 32) sBH[tid] = bh[tid];
    for (int k = tid; k < 1024; k += 256) {
        int m = k >> 5, px = k & 31, ly = px >> 3, lx = px & 7;
        s_hq[k] = hq[((size_t)b * MID + m) * HW + (y0 + ly) * WW + x0 + lx];
    }
    for (int k = tid; k < 1920; k += 256) {
        int m = k / 60, s = k % 60, yy = s / 10, xx = s % 10;
        int gy = y0 - 1 + yy, gx = x0 - 1 + xx;
        s_hk[k] = (gy >= 0 && gy < HH && gx >= 0 && gx < WW)
                  ? hk[((size_t)b * MID + m) * HW + gy * WW + gx] : 0.f;
    }
    __syncthreads();
    // build sH = relu(hq + hk_shift + bh): [p][m][px]
    for (int k = tid; k < 9216; k += 256) {
        int p = k >> 10, m = (k >> 5) & 31, px = k & 31;
        int ly = px >> 3, lx = px & 7;
        int di = p / 3, dj = p % 3;       // halo-relative (already includes -1 offset)
        float val = s_hq[m * 32 + px] + s_hk[m * 60 + (ly + di) * 10 + (lx + dj)] + sBH[m];
        sH[k] = fmaxf(val, 0.f);
    }

    float acc[4][4];
    #pragma unroll
    for (int oo = 0; oo < 4; oo++)
        #pragma unroll
        for (int i = 0; i < 4; i++) acc[oo][i] = 0.f;

    const int ly = tq >> 1;
    const int lx0 = (tq & 1) * 4;
    const float* vb = v + (size_t)b * OG * HW;
    for (int g = 0; g < GCN; g++) {
        __syncthreads();   // protects staging overlay on first iter, sV/sWt reuse after
        for (int k = tid; k < 128 * 60; k += 256) {
            int o = k / 60, s = k % 60, yy = s / 10, xx = s % 10;
            int gy = y0 - 1 + yy, gx = x0 - 1 + xx;
            float val = 0.f;
            if (gy >= 0 && gy < HH && gx >= 0 && gx < WW)
                val = vb[(size_t)(o * GCN + g) * HW + gy * WW + gx];
            sV[o * 62 + s] = val;
        }
        for (int k = tid; k < 4096; k += 256) {
            int m = k >> 7, o = k & 127;
            sWt[m * 132 + o] = W2t[(g * MID + m) * COUT + o];
        }
        __syncthreads();

        float c1r[4], c0r[4];
        #pragma unroll
        for (int oo = 0; oo < 4; oo++) {
            int o = to * 4 + oo;
            int og = o * GCN + g;
            float c1 = rinv[b * COUT + o] * gng[og];
            c1r[oo] = c1;
            c0r[oo] = c1 * b2[og] + gnb[og] - mu[b * COUT + o] * c1;
        }

        for (int p = 0; p < K2; p++) {
            float aacc[4][4];
            #pragma unroll
            for (int oo = 0; oo < 4; oo++)
                #pragma unroll
                for (int i = 0; i < 4; i++) aacc[oo][i] = 0.f;
            const float* sHp = sH + (p << 10);
            #pragma unroll
            for (int m = 0; m < 32; m++) {
                float4 hv = *(const float4*)&sHp[(m << 5) + 4 * tq];
                float4 w  = *(const float4*)&sWt[m * 132 + 4 * to];
                aacc[0][0] = fmaf(w.x, hv.x, aacc[0][0]); aacc[0][1] = fmaf(w.x, hv.y, aacc[0][1]);
                aacc[0][2] = fmaf(w.x, hv.z, aacc[0][2]); aacc[0][3] = fmaf(w.x, hv.w, aacc[0][3]);
                aacc[1][0] = fmaf(w.y, hv.x, aacc[1][0]); aacc[1][1] = fmaf(w.y, hv.y, aacc[1][1]);
                aacc[1][2] = fmaf(w.y, hv.z, aacc[1][2]); aacc[1][3] = fmaf(w.y, hv.w, aacc[1][3]);
                aacc[2][0] = fmaf(w.z, hv.x, aacc[2][0]); aacc[2][1] = fmaf(w.z, hv.y, aacc[2][1]);
                aacc[2][2] = fmaf(w.z, hv.z, aacc[2][2]); aacc[2][3] = fmaf(w.z, hv.w, aacc[2][3]);
                aacc[3][0] = fmaf(w.w, hv.x, aacc[3][0]); aacc[3][1] = fmaf(w.w, hv.y, aacc[3][1]);
                aacc[3][2] = fmaf(w.w, hv.z, aacc[3][2]); aacc[3][3] = fmaf(w.w, hv.w, aacc[3][3]);
            }
            int di = p / 3, dj = p % 3;   // halo-relative
            #pragma unroll
            for (int oo = 0; oo < 4; oo++) {
                int o = to * 4 + oo;
                float c1 = c1r[oo], c0 = c0r[oo];
                #pragma unroll
                for (int i = 0; i < 4; i++) {
                    float Vv = sV[o * 62 + (ly + di) * 10 + (lx0 + i + dj)];
                    float t = fmaf(c1, aacc[oo][i], c0);
                    acc[oo][i] = fmaf(t, Vv, acc[oo][i]);
                }
            }
        }
    }
    #pragma unroll
    for (int oo = 0; oo < 4; oo++) {
        float4 r;
        r.x = acc[oo][0]; r.y = acc[oo][1]; r.z = acc[oo][2]; r.w = acc[oo][3];
        *(float4*)&out[((size_t)b * COUT + to * 4 + oo) * HW + (y0 + ly) * WW + x0 + lx0] = r;
    }
}

// ---------------- launch ----------------
extern "C" void kernel_launch(void* const* d_in, const int* in_sizes, int n_in,
                              void* d_out, int out_size)
{
    const float* x     = (const float*)d_in[0];
    const float* Wk    = (const float*)d_in[1];
    const float* bn1g  = (const float*)d_in[2];
    const float* bn1b  = (const float*)d_in[3];
    const float* bn1m  = (const float*)d_in[4];
    const float* bn1v  = (const float*)d_in[5];
    const float* W1    = (const float*)d_in[6];
    const float* b1    = (const float*)d_in[7];
    const float* bn2g  = (const float*)d_in[8];
    const float* bn2b  = (const float*)d_in[9];
    const float* bn2m  = (const float*)d_in[10];
    const float* bn2v  = (const float*)d_in[11];
    const float* W2    = (const float*)d_in[12];
    const float* b2    = (const float*)d_in[13];
    const float* gng   = (const float*)d_in[14];
    const float* gnb   = (const float*)d_in[15];
    const float* Wv    = (const float*)d_in[16];
    const float* bnvg  = (const float*)d_in[17];
    const float* bnvb  = (const float*)d_in[18];
    const float* bnvm  = (const float*)d_in[19];
    const float* bnvv  = (const float*)d_in[20];
    float* out = (float*)d_out;

    float *ke, *vv, *hq, *hk, *pM, *pSh, *pmu, *pri;
    float *pWkt, *pW1qt, *pW1kt, *pWvt, *pW2t, *pbke, *pbv, *pbh;
    cudaGetSymbolAddress((void**)&ke,    g_ke);
    cudaGetSymbolAddress((void**)&vv,    g_v);
    cudaGetSymbolAddress((void**)&hq,    g_hq);
    cudaGetSymbolAddress((void**)&hk,    g_hk);
    cudaGetSymbolAddress((void**)&pM,    g_M);
    cudaGetSymbolAddress((void**)&pSh,   g_Sh);
    cudaGetSymbolAddress((void**)&pmu,   g_mu);
    cudaGetSymbolAddress((void**)&pri,   g_ri);
    cudaGetSymbolAddress((void**)&pWkt,  g_Wkt);
    cudaGetSymbolAddress((void**)&pW1qt, g_W1qt);
    cudaGetSymbolAddress((void**)&pW1kt, g_W1kt);
    cudaGetSymbolAddress((void**)&pWvt,  g_Wvt);
    cudaGetSymbolAddress((void**)&pW2t,  g_W2t);
    cudaGetSymbolAddress((void**)&pbke,  g_bke);
    cudaGetSymbolAddress((void**)&pbv,   g_bv);
    cudaGetSymbolAddress((void**)&pbh,   g_bh);

    static bool attr_set = false;
    if (!attr_set) {
        cudaFuncSetAttribute(main_kernel, cudaFuncAttributeMaxDynamicSharedMemorySize, 85632);
        attr_set = true;
    }

    zero_kernel<<<17, 256>>>(pM, BB * MID * MID + BB * MID);   // zeros g_M AND g_Sh (adjacent)
    zero_kernel<<<1, 128>>>(pSh, BB * MID);                    // ensure Sh zeroed regardless of layout
    fold_kernel<<<(107168 + 255) / 256, 256>>>(Wk, bn1g, bn1b, bn1m, bn1v,
                                               W1, b1, bn2g, bn2b, bn2m, bn2v,
                                               W2, Wv, bnvg, bnvb, bnvm, bnvv);
    pw_conv_kernel<64, true ><<<dim3(49, 2, BB), 256>>>(x,  pWkt,  pbke,    ke, CC_IN);
    pw_conv_kernel<64, false><<<dim3(49, 8, BB), 256>>>(x,  pWvt,  pbv,     vv, OG);
    pw_conv_kernel<32, false><<<dim3(49, 1, BB), 256>>>(x,  pW1qt, nullptr, hq, MID);
    pw_conv_kernel<32, false><<<dim3(49, 1, BB), 256>>>(ke, pW1kt, nullptr, hk, MID);
    fused_stats_kernel<<<dim3(28, BB), 256>>>(hq, hk, pbh, pM, pSh);
    stats_kernel<<<BB, 128>>>(W2, b2, pM, pSh, pmu, pri);
    main_kernel<<<dim3(7, 14, BB), 256, 85632>>>(hq, hk, vv, pW2t, b2, gng, gnb,
                                                 pmu, pri, pbh, out);
}

// round 4
// speedup vs baseline: 1.7931x; 1.3481x over previous
#include <cuda_runtime.h>
#include <cuda_bf16.h>
#include <math.h>

#define BB 4
#define CC_IN 128
#define HH 56
#define WW 56
#define HW 3136
#define MID 32
#define OG 512
#define COUT 128
#define GCN 4
#define K2 9
#define NPQ 28224
#define EPS 1e-5f

// ---------------- device scratch ----------------
__device__ float g_ke[BB * CC_IN * HW];
__device__ float g_v [BB * OG * HW];
__device__ float g_hq[BB * MID * HW];
__device__ float g_hk[BB * MID * HW];
__device__ float g_Wkt [CC_IN * CC_IN];      // [c][d]
__device__ float g_W1qt[CC_IN * MID];        // [c][m]
__device__ float g_W1kt[CC_IN * MID];        // [c][m]
__device__ float g_Wvt [CC_IN * OG];         // [c][o]
__device__ float g_W2t [GCN * MID * COUT];   // [g][m][o]
__device__ float g_bke[CC_IN];
__device__ float g_bh [MID];
__device__ float g_bv [OG];
__device__ float g_M  [BB * MID * MID];
__device__ float g_Sh [BB * MID];
__device__ float g_mu [BB * COUT];
__device__ float g_ri [BB * COUT];

// Fold BN affines into (transposed) weights + zero the M/Sh accumulators.
// index space: [0,16384) Wkt | [16384,20480) W1qt | [20480,24576) W1kt |
// [24576,90112) Wvt | [90112,106496) W2t | [106496,106624) bke |
// [106624,106656) bh | [106656,107168) bv | [107168,111264) zero M | [111264,111392) zero Sh
__global__ void fold_kernel(
    const float* __restrict__ Wk,
    const float* __restrict__ bn1g, const float* __restrict__ bn1b,
    const float* __restrict__ bn1m, const float* __restrict__ bn1v,
    const float* __restrict__ W1,  const float* __restrict__ b1,
    const float* __restrict__ bn2g, const float* __restrict__ bn2b,
    const float* __restrict__ bn2m, const float* __restrict__ bn2v,
    const float* __restrict__ W2,
    const float* __restrict__ Wv,
    const float* __restrict__ bnvg, const float* __restrict__ bnvb,
    const float* __restrict__ bnvm, const float* __restrict__ bnvv)
{
    int i = blockIdx.x * blockDim.x + threadIdx.x;
    if (i < 16384) {
        int d = i >> 7, c = i & 127;
        float s = bn1g[d] * rsqrtf(bn1v[d] + EPS);
        g_Wkt[c * 128 + d] = Wk[d * 128 + c] * s;
    } else if (i < 20480) {
        int j = i - 16384; int m = j >> 7, c = j & 127;
        float s = bn2g[m] * rsqrtf(bn2v[m] + EPS);
        g_W1qt[c * MID + m] = W1[m * 256 + c] * s;
    } else if (i < 24576) {
        int j = i - 20480; int m = j >> 7, c = j & 127;
        float s = bn2g[m] * rsqrtf(bn2v[m] + EPS);
        g_W1kt[c * MID + m] = W1[m * 256 + 128 + c] * s;
    } else if (i < 90112) {
        int j = i - 24576; int o = j >> 7, c = j & 127;
        float s = bnvg[o] * rsqrtf(bnvv[o] + EPS);
        g_Wvt[c * OG + o] = Wv[o * 128 + c] * s;
    } else if (i < 106496) {
        int j = i - 90112; int o = j & 127, t = j >> 7;
        int g = t >> 5, m = t & 31;
        g_W2t[(g * MID + m) * COUT + o] = W2[(o * GCN + g) * MID + m];
    } else if (i < 106624) {
        int d = i - 106496;
        float s = bn1g[d] * rsqrtf(bn1v[d] + EPS);
        g_bke[d] = bn1b[d] - bn1m[d] * s;
    } else if (i < 106656) {
        int m = i - 106624;
        float s = bn2g[m] * rsqrtf(bn2v[m] + EPS);
        g_bh[m] = s * b1[m] + bn2b[m] - bn2m[m] * s;
    } else if (i < 107168) {
        int o = i - 106656;
        float s = bnvg[o] * rsqrtf(bnvv[o] + EPS);
        g_bv[o] = bnvb[o] - bnvm[o] * s;
    } else if (i < 111264) {
        g_M[i - 107168] = 0.f;
    } else if (i < 111392) {
        g_Sh[i - 111264] = 0.f;
    }
}

// ---------------- pointwise-conv GEMM: 128 threads, 8(or 4) d x 4 px per thread ----------------
// Wt TRANSPOSED [c][Dtot]. grid (HW/64, Dtot/DTILE, B).
template<int DTILE, bool RELU>
__global__ void __launch_bounds__(128) pw_conv_kernel(
    const float* __restrict__ X, const float* __restrict__ Wt,
    const float* __restrict__ bias, float* __restrict__ Y, int Dtot)
{
    constexpr int PX = 64;
    constexpr int CCH = 64;
    constexpr int DN = DTILE / 8;     // 8 for DTILE=64, 4 for DTILE=32
    __shared__ float sX[CCH * PX];
    __shared__ float sW[CCH * DTILE];
    const int b   = blockIdx.z;
    const int hw0 = blockIdx.x * PX;
    const int d0  = blockIdx.y * DTILE;
    const int tid = threadIdx.x;
    const int tx  = tid & 15;   // px group: 4 contiguous px
    const int td  = tid >> 4;   // 0..7, owns DN contiguous d's
    float acc[DN][4];
    #pragma unroll
    for (int j = 0; j < DN; j++)
        #pragma unroll
        for (int i = 0; i < 4; i++) acc[j][i] = 0.f;
    const float* Xb = X + (size_t)b * CC_IN * HW;
    for (int cc = 0; cc < CC_IN; cc += CCH) {
        // stage X: 1024 float4s
        for (int k = tid; k < CCH * PX / 4; k += 128) {
            int c = k >> 4, q = k & 15;
            *(float4*)&sX[c * 64 + q * 4] =
                *(const float4*)&Xb[(size_t)(cc + c) * HW + hw0 + q * 4];
        }
        // stage W: CCH*DTILE/4 float4s
        for (int k = tid; k < CCH * DTILE / 4; k += 128) {
            int c = k / (DTILE / 4), q = k % (DTILE / 4);
            *(float4*)&sW[c * DTILE + q * 4] =
                *(const float4*)&Wt[(size_t)(cc + c) * Dtot + d0 + q * 4];
        }
        __syncthreads();
        #pragma unroll 4
        for (int c = 0; c < CCH; c++) {
            float4 xv = *(const float4*)&sX[c * 64 + 4 * tx];
            float4 w0 = *(const float4*)&sW[c * DTILE + DN * td];
            acc[0][0] = fmaf(w0.x, xv.x, acc[0][0]); acc[0][1] = fmaf(w0.x, xv.y, acc[0][1]);
            acc[0][2] = fmaf(w0.x, xv.z, acc[0][2]); acc[0][3] = fmaf(w0.x, xv.w, acc[0][3]);
            acc[1][0] = fmaf(w0.y, xv.x, acc[1][0]); acc[1][1] = fmaf(w0.y, xv.y, acc[1][1]);
            acc[1][2] = fmaf(w0.y, xv.z, acc[1][2]); acc[1][3] = fmaf(w0.y, xv.w, acc[1][3]);
            acc[2][0] = fmaf(w0.z, xv.x, acc[2][0]); acc[2][1] = fmaf(w0.z, xv.y, acc[2][1]);
            acc[2][2] = fmaf(w0.z, xv.z, acc[2][2]); acc[2][3] = fmaf(w0.z, xv.w, acc[2][3]);
            acc[3][0] = fmaf(w0.w, xv.x, acc[3][0]); acc[3][1] = fmaf(w0.w, xv.y, acc[3][1]);
            acc[3][2] = fmaf(w0.w, xv.z, acc[3][2]); acc[3][3] = fmaf(w0.w, xv.w, acc[3][3]);
            if (DN == 8) {
                float4 w1 = *(const float4*)&sW[c * DTILE + DN * td + 4];
                acc[4][0] = fmaf(w1.x, xv.x, acc[4][0]); acc[4][1] = fmaf(w1.x, xv.y, acc[4][1]);
                acc[4][2] = fmaf(w1.x, xv.z, acc[4][2]); acc[4][3] = fmaf(w1.x, xv.w, acc[4][3]);
                acc[5][0] = fmaf(w1.y, xv.x, acc[5][0]); acc[5][1] = fmaf(w1.y, xv.y, acc[5][1]);
                acc[5][2] = fmaf(w1.y, xv.z, acc[5][2]); acc[5][3] = fmaf(w1.y, xv.w, acc[5][3]);
                acc[6][0] = fmaf(w1.z, xv.x, acc[6][0]); acc[6][1] = fmaf(w1.z, xv.y, acc[6][1]);
                acc[6][2] = fmaf(w1.z, xv.z, acc[6][2]); acc[6][3] = fmaf(w1.z, xv.w, acc[6][3]);
                acc[7][0] = fmaf(w1.w, xv.x, acc[7][0]); acc[7][1] = fmaf(w1.w, xv.y, acc[7][1]);
                acc[7][2] = fmaf(w1.w, xv.z, acc[7][2]); acc[7][3] = fmaf(w1.w, xv.w, acc[7][3]);
            }
        }
        __syncthreads();
    }
    #pragma unroll
    for (int j = 0; j < DN; j++) {
        int d = d0 + td * DN + j;
        float bsv = bias ? bias[d] : 0.f;
        float4 r;
        r.x = acc[j][0] + bsv; r.y = acc[j][1] + bsv;
        r.z = acc[j][2] + bsv; r.w = acc[j][3] + bsv;
        if (RELU) {
            r.x = fmaxf(r.x, 0.f); r.y = fmaxf(r.y, 0.f);
            r.z = fmaxf(r.z, 0.f); r.w = fmaxf(r.w, 0.f);
        }
        *(float4*)&Y[((size_t)b * Dtot + d) * HW + hw0 + 4 * tx] = r;
    }
}

// ---------------- fused GroupNorm stats: Sh + Gram M directly from hq/hk ----------------
__global__ void fused_stats_kernel(const float* __restrict__ hq, const float* __restrict__ hk,
                                   const float* __restrict__ bh,
                                   float* __restrict__ M, float* __restrict__ Sh)
{
    __shared__ float s_hq[32 * 112];
    __shared__ float s_hk[32 * 224];
    __shared__ float sBH[32];
    __shared__ float sSh[32];
    __shared__ float sM[1024];
    const int b  = blockIdx.y;
    const int y0 = blockIdx.x * 2;
    const int tid = threadIdx.x;
    if (tid < 32) { sBH[tid] = bh[tid]; sSh[tid] = 0.f; }
    for (int k = tid; k < 1024; k += 256) sM[k] = 0.f;
    for (int k = tid; k < 32 * 112; k += 256) {
        int m = k / 112, s = k % 112, r = s / 56, x = s % 56;
        s_hq[k] = hq[((size_t)b * MID + m) * HW + (y0 + r) * WW + x];
    }
    for (int k = tid; k < 32 * 224; k += 256) {
        int m = k / 224, s = k % 224, rr = s / 56, x = s % 56;
        int yy = y0 - 1 + rr;
        s_hk[k] = (yy >= 0 && yy < HH) ? hk[((size_t)b * MID + m) * HW + yy * WW + x] : 0.f;
    }
    __syncthreads();
    {
        int m = tid & 31, ch = tid >> 5;
        float s = 0.f;
        float base = sBH[m];
        for (int px = ch * 14; px < ch * 14 + 14; px++) {
            int r = px / 56, x = px % 56;
            float hqv = s_hq[m * 112 + px] + base;
            #pragma unroll
            for (int p = 0; p < 9; p++) {
                int di = p / 3, dj = p % 3;
                int xx = x + dj - 1;
                float hkv = (xx >= 0 && xx < WW) ? s_hk[m * 224 + (r + di) * 56 + xx] : 0.f;
                s += fmaxf(hqv + hkv, 0.f);
            }
        }
        atomicAdd(&sSh[m], s);
    }
    {
        int combo = tid & 63;
        int it = combo & 7, jt = combo >> 3;
        int pg = tid >> 6;
        float accM[4][4];
        #pragma unroll
        for (int a = 0; a < 4; a++)
            #pragma unroll
            for (int c = 0; c < 4; c++) accM[a][c] = 0.f;
        for (int px = pg * 28; px < pg * 28 + 28; px++) {
            int r = px / 56, x = px % 56;
            for (int p = 0; p < 9; p++) {
                int di = p / 3, dj = p % 3;
                int xx = x + dj - 1;
                bool in = (xx >= 0 && xx < WW);
                float hi[4], hj[4];
                #pragma unroll
                for (int a = 0; a < 4; a++) {
                    int m = it * 4 + a;
                    float hkv = in ? s_hk[m * 224 + (r + di) * 56 + xx] : 0.f;
                    hi[a] = fmaxf(s_hq[m * 112 + px] + hkv + sBH[m], 0.f);
                }
                #pragma unroll
                for (int c = 0; c < 4; c++) {
                    int m = jt * 4 + c;
                    float hkv = in ? s_hk[m * 224 + (r + di) * 56 + xx] : 0.f;
                    hj[c] = fmaxf(s_hq[m * 112 + px] + hkv + sBH[m], 0.f);
                }
                #pragma unroll
                for (int a = 0; a < 4; a++)
                    #pragma unroll
                    for (int c = 0; c < 4; c++) accM[a][c] = fmaf(hi[a], hj[c], accM[a][c]);
            }
        }
        #pragma unroll
        for (int a = 0; a < 4; a++)
            #pragma unroll
            for (int c = 0; c < 4; c++)
                atomicAdd(&sM[(it * 4 + a) * 32 + jt * 4 + c], accM[a][c]);
    }
    __syncthreads();
    if (tid < 32) atomicAdd(&Sh[b * 32 + tid], sSh[tid]);
    for (int k = tid; k < 1024; k += 256) atomicAdd(&M[b * 1024 + k], sM[k]);
}

// ---------------- GroupNorm stats via quadratic forms ----------------
__global__ void stats_kernel(const float* __restrict__ W2, const float* __restrict__ b2,
                             const float* __restrict__ M, const float* __restrict__ Sh,
                             float* __restrict__ mu, float* __restrict__ rinv)
{
    int b = blockIdx.x, o = threadIdx.x;
    __shared__ float sM[1024], sSh[32];
    for (int k = o; k < 1024; k += 128) sM[k] = M[b * 1024 + k];
    if (o < 32) sSh[o] = Sh[b * 32 + o];
    __syncthreads();
    float S1 = 0.f, S2 = 0.f;
    const float NPf = (float)NPQ;
    for (int g = 0; g < GCN; g++) {
        int og = o * GCN + g;
        float w[32];
        #pragma unroll
        for (int m = 0; m < 32; m++) w[m] = W2[og * 32 + m];
        float d1 = 0.f;
        #pragma unroll
        for (int m = 0; m < 32; m++) d1 = fmaf(w[m], sSh[m], d1);
        float q = 0.f;
        for (int i2 = 0; i2 < 32; i2++) {
            float ti = 0.f;
            #pragma unroll
            for (int j = 0; j < 32; j++) ti = fmaf(sM[i2 * 32 + j], w[j], ti);
            q = fmaf(w[i2], ti, q);
        }
        float bbv = b2[og];
        S1 += d1 + bbv * NPf;
        S2 += q + 2.f * bbv * d1 + bbv * bbv * NPf;
    }
    const float N = (float)(GCN * NPQ);
    float m_ = S1 / N;
    float var = S2 / N - m_ * m_;
    mu[b * COUT + o]   = m_;
    rinv[b * COUT + o] = rsqrtf(var + EPS);
}

// ---------------- main fused kernel: 128 threads, 8 o x 4 px per thread, p in triples ----------------
// grid (7, 14, B): 8x4 px tile, all 128 couts.
// smem: sH [p][m][32] 9216 | sV [o][62] 7936 | sWt [m][132] 4224 | sBH 32 = 85632 B
__global__ void __launch_bounds__(128) main_kernel(
    const float* __restrict__ hq, const float* __restrict__ hk,
    const float* __restrict__ v,
    const float* __restrict__ W2t, const float* __restrict__ b2,
    const float* __restrict__ gng, const float* __restrict__ gnb,
    const float* __restrict__ mu, const float* __restrict__ rinv,
    const float* __restrict__ bh, float* __restrict__ out)
{
    extern __shared__ float smem[];
    float* sH  = smem;                       // 9216
    float* sV  = smem + 9216;                // 7936
    float* sWt = smem + 17152;               // 4224
    float* sBH = smem + 21376;               // 32
    float* s_hq = sV;                        // staging overlay (1024)
    float* s_hk = sV + 1024;                 // staging overlay (1920)
    const int b   = blockIdx.z;
    const int x0  = blockIdx.x * 8;
    const int y0  = blockIdx.y * 4;
    const int tid = threadIdx.x;
    const int tq  = tid & 7;                 // px group
    const int to  = tid >> 3;                // 0..15, owns 8 couts
    const int ly  = tq >> 1;
    const int lx0 = (tq & 1) * 4;

    if (tid < 32) sBH[tid] = bh[tid];
    for (int k = tid; k < 1024; k += 128) {
        int m = k >> 5, px = k & 31, lyy = px >> 3, lxx = px & 7;
        s_hq[k] = hq[((size_t)b * MID + m) * HW + (y0 + lyy) * WW + x0 + lxx];
    }
    for (int k = tid; k < 1920; k += 128) {
        int m = k / 60, s = k % 60, yy = s / 10, xx = s % 10;
        int gy = y0 - 1 + yy, gx = x0 - 1 + xx;
        s_hk[k] = (gy >= 0 && gy < HH && gx >= 0 && gx < WW)
                  ? hk[((size_t)b * MID + m) * HW + gy * WW + gx] : 0.f;
    }
    __syncthreads();
    for (int k = tid; k < 9216; k += 128) {
        int p = k >> 10, m = (k >> 5) & 31, px = k & 31;
        int lyy = px >> 3, lxx = px & 7;
        int di = p / 3, dj = p % 3;
        float val = s_hq[m * 32 + px] + s_hk[m * 60 + (lyy + di) * 10 + (lxx + dj)] + sBH[m];
        sH[k] = fmaxf(val, 0.f);
    }

    float acc[8][4];
    #pragma unroll
    for (int oo = 0; oo < 8; oo++)
        #pragma unroll
        for (int i = 0; i < 4; i++) acc[oo][i] = 0.f;

    const float* vb = v + (size_t)b * OG * HW;
    for (int g = 0; g < GCN; g++) {
        __syncthreads();
        for (int k = tid; k < 128 * 60; k += 128) {
            int o = k / 60, s = k % 60, yy = s / 10, xx = s % 10;
            int gy = y0 - 1 + yy, gx = x0 - 1 + xx;
            float val = 0.f;
            if (gy >= 0 && gy < HH && gx >= 0 && gx < WW)
                val = vb[(size_t)(o * GCN + g) * HW + gy * WW + gx];
            sV[o * 62 + s] = val;
        }
        for (int k = tid; k < 4096; k += 128) {
            int m = k >> 7, o = k & 127;
            sWt[m * 132 + o] = W2t[(g * MID + m) * COUT + o];
        }
        __syncthreads();

        float c1r[8], c0r[8];
        #pragma unroll
        for (int oo = 0; oo < 8; oo++) {
            int o = to * 8 + oo;
            int og = o * GCN + g;
            float c1 = rinv[b * COUT + o] * gng[og];
            c1r[oo] = c1;
            c0r[oo] = c1 * b2[og] + gnb[og] - mu[b * COUT + o] * c1;
        }

        #pragma unroll
        for (int sweep = 0; sweep < 3; sweep++) {   // di = sweep
            float aacc[3][8][4];
            #pragma unroll
            for (int pp = 0; pp < 3; pp++)
                #pragma unroll
                for (int oo = 0; oo < 8; oo++)
                    #pragma unroll
                    for (int i = 0; i < 4; i++) aacc[pp][oo][i] = 0.f;
            #pragma unroll 4
            for (int m = 0; m < 32; m++) {
                float4 w0 = *(const float4*)&sWt[m * 132 + 8 * to];
                float4 w1 = *(const float4*)&sWt[m * 132 + 8 * to + 4];
                #pragma unroll
                for (int pp = 0; pp < 3; pp++) {
                    float4 hv = *(const float4*)&sH[((sweep * 3 + pp) << 10) + (m << 5) + 4 * tq];
                    float* a0 = &aacc[pp][0][0];
                    a0[0]  = fmaf(w0.x, hv.x, a0[0]);  a0[1]  = fmaf(w0.x, hv.y, a0[1]);
                    a0[2]  = fmaf(w0.x, hv.z, a0[2]);  a0[3]  = fmaf(w0.x, hv.w, a0[3]);
                    a0[4]  = fmaf(w0.y, hv.x, a0[4]);  a0[5]  = fmaf(w0.y, hv.y, a0[5]);
                    a0[6]  = fmaf(w0.y, hv.z, a0[6]);  a0[7]  = fmaf(w0.y, hv.w, a0[7]);
                    a0[8]  = fmaf(w0.z, hv.x, a0[8]);  a0[9]  = fmaf(w0.z, hv.y, a0[9]);
                    a0[10] = fmaf(w0.z, hv.z, a0[10]); a0[11] = fmaf(w0.z, hv.w, a0[11]);
                    a0[12] = fmaf(w0.w, hv.x, a0[12]); a0[13] = fmaf(w0.w, hv.y, a0[13]);
                    a0[14] = fmaf(w0.w, hv.z, a0[14]); a0[15] = fmaf(w0.w, hv.w, a0[15]);
                    a0[16] = fmaf(w1.x, hv.x, a0[16]); a0[17] = fmaf(w1.x, hv.y, a0[17]);
                    a0[18] = fmaf(w1.x, hv.z, a0[18]); a0[19] = fmaf(w1.x, hv.w, a0[19]);
                    a0[20] = fmaf(w1.y, hv.x, a0[20]); a0[21] = fmaf(w1.y, hv.y, a0[21]);
                    a0[22] = fmaf(w1.y, hv.z, a0[22]); a0[23] = fmaf(w1.y, hv.w, a0[23]);
                    a0[24] = fmaf(w1.z, hv.x, a0[24]); a0[25] = fmaf(w1.z, hv.y, a0[25]);
                    a0[26] = fmaf(w1.z, hv.z, a0[26]); a0[27] = fmaf(w1.z, hv.w, a0[27]);
                    a0[28] = fmaf(w1.w, hv.x, a0[28]); a0[29] = fmaf(w1.w, hv.y, a0[29]);
                    a0[30] = fmaf(w1.w, hv.z, a0[30]); a0[31] = fmaf(w1.w, hv.w, a0[31]);
                }
            }
            #pragma unroll
            for (int pp = 0; pp < 3; pp++) {        // dj = pp
                #pragma unroll
                for (int oo = 0; oo < 8; oo++) {
                    int o = to * 8 + oo;
                    float c1 = c1r[oo], c0 = c0r[oo];
                    #pragma unroll
                    for (int i = 0; i < 4; i++) {
                        float Vv = sV[o * 62 + (ly + sweep) * 10 + (lx0 + i + pp)];
                        float t = fmaf(c1, aacc[pp][oo][i], c0);
                        acc[oo][i] = fmaf(t, Vv, acc[oo][i]);
                    }
                }
            }
        }
    }
    #pragma unroll
    for (int oo = 0; oo < 8; oo++) {
        float4 r;
        r.x = acc[oo][0]; r.y = acc[oo][1]; r.z = acc[oo][2]; r.w = acc[oo][3];
        *(float4*)&out[((size_t)b * COUT + to * 8 + oo) * HW + (y0 + ly) * WW + x0 + lx0] = r;
    }
}

// ---------------- launch ----------------
extern "C" void kernel_launch(void* const* d_in, const int* in_sizes, int n_in,
                              void* d_out, int out_size)
{
    const float* x     = (const float*)d_in[0];
    const float* Wk    = (const float*)d_in[1];
    const float* bn1g  = (const float*)d_in[2];
    const float* bn1b  = (const float*)d_in[3];
    const float* bn1m  = (const float*)d_in[4];
    const float* bn1v  = (const float*)d_in[5];
    const float* W1    = (const float*)d_in[6];
    const float* b1    = (const float*)d_in[7];
    const float* bn2g  = (const float*)d_in[8];
    const float* bn2b  = (const float*)d_in[9];
    const float* bn2m  = (const float*)d_in[10];
    const float* bn2v  = (const float*)d_in[11];
    const float* W2    = (const float*)d_in[12];
    const float* b2    = (const float*)d_in[13];
    const float* gng   = (const float*)d_in[14];
    const float* gnb   = (const float*)d_in[15];
    const float* Wv    = (const float*)d_in[16];
    const float* bnvg  = (const float*)d_in[17];
    const float* bnvb  = (const float*)d_in[18];
    const float* bnvm  = (const float*)d_in[19];
    const float* bnvv  = (const float*)d_in[20];
    float* out = (float*)d_out;

    float *ke, *vv, *hq, *hk, *pM, *pSh, *pmu, *pri;
    float *pWkt, *pW1qt, *pW1kt, *pWvt, *pW2t, *pbke, *pbv, *pbh;
    cudaGetSymbolAddress((void**)&ke,    g_ke);
    cudaGetSymbolAddress((void**)&vv,    g_v);
    cudaGetSymbolAddress((void**)&hq,    g_hq);
    cudaGetSymbolAddress((void**)&hk,    g_hk);
    cudaGetSymbolAddress((void**)&pM,    g_M);
    cudaGetSymbolAddress((void**)&pSh,   g_Sh);
    cudaGetSymbolAddress((void**)&pmu,   g_mu);
    cudaGetSymbolAddress((void**)&pri,   g_ri);
    cudaGetSymbolAddress((void**)&pWkt,  g_Wkt);
    cudaGetSymbolAddress((void**)&pW1qt, g_W1qt);
    cudaGetSymbolAddress((void**)&pW1kt, g_W1kt);
    cudaGetSymbolAddress((void**)&pWvt,  g_Wvt);
    cudaGetSymbolAddress((void**)&pW2t,  g_W2t);
    cudaGetSymbolAddress((void**)&pbke,  g_bke);
    cudaGetSymbolAddress((void**)&pbv,   g_bv);
    cudaGetSymbolAddress((void**)&pbh,   g_bh);

    static bool attr_set = false;
    if (!attr_set) {
        cudaFuncSetAttribute(main_kernel, cudaFuncAttributeMaxDynamicSharedMemorySize, 85632);
        attr_set = true;
    }

    fold_kernel<<<(111392 + 255) / 256, 256>>>(Wk, bn1g, bn1b, bn1m, bn1v,
                                               W1, b1, bn2g, bn2b, bn2m, bn2v,
                                               W2, Wv, bnvg, bnvb, bnvm, bnvv);
    pw_conv_kernel<64, true ><<<dim3(49, 2, BB), 128>>>(x,  pWkt,  pbke,    ke, CC_IN);
    pw_conv_kernel<64, false><<<dim3(49, 8, BB), 128>>>(x,  pWvt,  pbv,     vv, OG);
    pw_conv_kernel<32, false><<<dim3(49, 1, BB), 128>>>(x,  pW1qt, nullptr, hq, MID);
    pw_conv_kernel<32, false><<<dim3(49, 1, BB), 128>>>(ke, pW1kt, nullptr, hk, MID);
    fused_stats_kernel<<<dim3(28, BB), 256>>>(hq, hk, pbh, pM, pSh);
    stats_kernel<<<BB, 128>>>(W2, b2, pM, pSh, pmu, pri);
    main_kernel<<<dim3(7, 14, BB), 128, 85632>>>(hq, hk, vv, pW2t, b2, gng, gnb,
                                                 pmu, pri, pbh, out);
}

// round 6
// speedup vs baseline: 2.1170x; 1.1806x over previous
#include <cuda_runtime.h>
#include <cuda_bf16.h>
#include <math.h>

#define BB 4
#define CC_IN 128
#define HH 56
#define WW 56
#define HW 3136
#define MID 32
#define OG 512
#define COUT 128
#define GCN 4
#define K2 9
#define NPQ 28224
#define EPS 1e-5f

// ---------------- device scratch ----------------
__device__ float g_v [BB * OG * HW];
__device__ float g_hq[BB * MID * HW];
__device__ float g_hk[BB * MID * HW];
__device__ float g_Wkt [CC_IN * CC_IN];      // [c][d]
__device__ float g_W1qt[CC_IN * MID];        // [c][m]
__device__ float g_W1kt[CC_IN * MID];        // [c][m]
__device__ float g_Wvt [CC_IN * OG];         // [c][o]
__device__ float g_W2t [GCN * MID * COUT];   // [g][m][o]
__device__ float g_bke[CC_IN];
__device__ float g_bh [MID];
__device__ float g_bv [OG];
__device__ float g_M  [BB * MID * MID];
__device__ float g_Sh [BB * MID];
__device__ float g_mu [BB * COUT];
__device__ float g_ri [BB * COUT];

// Fold BN affines into (transposed) weights + zero M/Sh accumulators.
__global__ void fold_kernel(
    const float* __restrict__ Wk,
    const float* __restrict__ bn1g, const float* __restrict__ bn1b,
    const float* __restrict__ bn1m, const float* __restrict__ bn1v,
    const float* __restrict__ W1,  const float* __restrict__ b1,
    const float* __restrict__ bn2g, const float* __restrict__ bn2b,
    const float* __restrict__ bn2m, const float* __restrict__ bn2v,
    const float* __restrict__ W2,
    const float* __restrict__ Wv,
    const float* __restrict__ bnvg, const float* __restrict__ bnvb,
    const float* __restrict__ bnvm, const float* __restrict__ bnvv)
{
    int i = blockIdx.x * blockDim.x + threadIdx.x;
    if (i < 16384) {
        int d = i >> 7, c = i & 127;
        float s = bn1g[d] * rsqrtf(bn1v[d] + EPS);
        g_Wkt[c * 128 + d] = Wk[d * 128 + c] * s;
    } else if (i < 20480) {
        int j = i - 16384; int m = j >> 7, c = j & 127;
        float s = bn2g[m] * rsqrtf(bn2v[m] + EPS);
        g_W1qt[c * MID + m] = W1[m * 256 + c] * s;
    } else if (i < 24576) {
        int j = i - 20480; int m = j >> 7, c = j & 127;
        float s = bn2g[m] * rsqrtf(bn2v[m] + EPS);
        g_W1kt[c * MID + m] = W1[m * 256 + 128 + c] * s;
    } else if (i < 90112) {
        int j = i - 24576; int o = j >> 7, c = j & 127;
        float s = bnvg[o] * rsqrtf(bnvv[o] + EPS);
        g_Wvt[c * OG + o] = Wv[o * 128 + c] * s;
    } else if (i < 106496) {
        int j = i - 90112; int o = j & 127, t = j >> 7;
        int g = t >> 5, m = t & 31;
        g_W2t[(g * MID + m) * COUT + o] = W2[(o * GCN + g) * MID + m];
    } else if (i < 106624) {
        int d = i - 106496;
        float s = bn1g[d] * rsqrtf(bn1v[d] + EPS);
        g_bke[d] = bn1b[d] - bn1m[d] * s;
    } else if (i < 106656) {
        int m = i - 106624;
        float s = bn2g[m] * rsqrtf(bn2v[m] + EPS);
        g_bh[m] = s * b1[m] + bn2b[m] - bn2m[m] * s;
    } else if (i < 107168) {
        int o = i - 106656;
        float s = bnvg[o] * rsqrtf(bnvv[o] + EPS);
        g_bv[o] = bnvb[o] - bnvm[o] * s;
    } else if (i < 111264) {
        g_M[i - 107168] = 0.f;
    } else if (i < 111392) {
        g_Sh[i - 111264] = 0.f;
    }
}

// ---------------- front kernel: ke (regs/smem only) + hq + hk in one pass ----------------
// grid (49, B), 256 threads. px tile 64.
// dyn smem: sX 4096 | sWk 8192 | sW1q 2048 = 14336 floats = 57344 B
// overlays after phase A: sKE -> sWk region, sW1k -> sX region.
__global__ void __launch_bounds__(256) front_kernel(
    const float* __restrict__ X,
    float* __restrict__ hq_out, float* __restrict__ hk_out)
{
    extern __shared__ float fsm[];
    float* sX   = fsm;            // 4096
    float* sWk  = fsm + 4096;     // 8192
    float* sW1q = fsm + 12288;    // 2048
    float* sW1k = fsm;            // overlay of sX (4096 = 128*32)
    float* sKE  = fsm + 4096;     // overlay of sWk (8192 = 128*64)
    const int b   = blockIdx.y;
    const int hw0 = blockIdx.x * 64;
    const int tid = threadIdx.x;
    const int tx  = tid & 15;     // px group (4 contiguous)
    const int td  = tid >> 4;     // 0..15

    float keacc[8][4];
    float hqacc[2][4];
    #pragma unroll
    for (int j = 0; j < 8; j++)
        #pragma unroll
        for (int i = 0; i < 4; i++) keacc[j][i] = 0.f;
    #pragma unroll
    for (int j = 0; j < 2; j++)
        #pragma unroll
        for (int i = 0; i < 4; i++) hqacc[j][i] = 0.f;

    const float* Xb = X + (size_t)b * CC_IN * HW;
    for (int cc = 0; cc < 128; cc += 64) {
        for (int k = tid; k < 1024; k += 256) {       // sX: 64c x 64px
            int c = k >> 4, q = k & 15;
            *(float4*)&sX[c * 64 + q * 4] = *(const float4*)&Xb[(size_t)(cc + c) * HW + hw0 + q * 4];
        }
        for (int k = tid; k < 2048; k += 256) {       // sWk: 64c x 128d
            int c = k >> 5, q = k & 31;
            *(float4*)&sWk[c * 128 + q * 4] = *(const float4*)&g_Wkt[(cc + c) * 128 + q * 4];
        }
        for (int k = tid; k < 512; k += 256) {        // sW1q: 64c x 32m
            int c = k >> 3, q = k & 7;
            *(float4*)&sW1q[c * 32 + q * 4] = *(const float4*)&g_W1qt[(cc + c) * 32 + q * 4];
        }
        __syncthreads();
        #pragma unroll 4
        for (int c = 0; c < 64; c++) {
            float4 xv = *(const float4*)&sX[c * 64 + 4 * tx];
            float4 w0 = *(const float4*)&sWk[c * 128 + 8 * td];
            float4 w1 = *(const float4*)&sWk[c * 128 + 8 * td + 4];
            keacc[0][0] = fmaf(w0.x, xv.x, keacc[0][0]); keacc[0][1] = fmaf(w0.x, xv.y, keacc[0][1]);
            keacc[0][2] = fmaf(w0.x, xv.z, keacc[0][2]); keacc[0][3] = fmaf(w0.x, xv.w, keacc[0][3]);
            keacc[1][0] = fmaf(w0.y, xv.x, keacc[1][0]); keacc[1][1] = fmaf(w0.y, xv.y, keacc[1][1]);
            keacc[1][2] = fmaf(w0.y, xv.z, keacc[1][2]); keacc[1][3] = fmaf(w0.y, xv.w, keacc[1][3]);
            keacc[2][0] = fmaf(w0.z, xv.x, keacc[2][0]); keacc[2][1] = fmaf(w0.z, xv.y, keacc[2][1]);
            keacc[2][2] = fmaf(w0.z, xv.z, keacc[2][2]); keacc[2][3] = fmaf(w0.z, xv.w, keacc[2][3]);
            keacc[3][0] = fmaf(w0.w, xv.x, keacc[3][0]); keacc[3][1] = fmaf(w0.w, xv.y, keacc[3][1]);
            keacc[3][2] = fmaf(w0.w, xv.z, keacc[3][2]); keacc[3][3] = fmaf(w0.w, xv.w, keacc[3][3]);
            keacc[4][0] = fmaf(w1.x, xv.x, keacc[4][0]); keacc[4][1] = fmaf(w1.x, xv.y, keacc[4][1]);
            keacc[4][2] = fmaf(w1.x, xv.z, keacc[4][2]); keacc[4][3] = fmaf(w1.x, xv.w, keacc[4][3]);
            keacc[5][0] = fmaf(w1.y, xv.x, keacc[5][0]); keacc[5][1] = fmaf(w1.y, xv.y, keacc[5][1]);
            keacc[5][2] = fmaf(w1.y, xv.z, keacc[5][2]); keacc[5][3] = fmaf(w1.y, xv.w, keacc[5][3]);
            keacc[6][0] = fmaf(w1.z, xv.x, keacc[6][0]); keacc[6][1] = fmaf(w1.z, xv.y, keacc[6][1]);
            keacc[6][2] = fmaf(w1.z, xv.z, keacc[6][2]); keacc[6][3] = fmaf(w1.z, xv.w, keacc[6][3]);
            keacc[7][0] = fmaf(w1.w, xv.x, keacc[7][0]); keacc[7][1] = fmaf(w1.w, xv.y, keacc[7][1]);
            keacc[7][2] = fmaf(w1.w, xv.z, keacc[7][2]); keacc[7][3] = fmaf(w1.w, xv.w, keacc[7][3]);
            float2 wq = *(const float2*)&sW1q[c * 32 + 2 * td];
            hqacc[0][0] = fmaf(wq.x, xv.x, hqacc[0][0]); hqacc[0][1] = fmaf(wq.x, xv.y, hqacc[0][1]);
            hqacc[0][2] = fmaf(wq.x, xv.z, hqacc[0][2]); hqacc[0][3] = fmaf(wq.x, xv.w, hqacc[0][3]);
            hqacc[1][0] = fmaf(wq.y, xv.x, hqacc[1][0]); hqacc[1][1] = fmaf(wq.y, xv.y, hqacc[1][1]);
            hqacc[1][2] = fmaf(wq.y, xv.z, hqacc[1][2]); hqacc[1][3] = fmaf(wq.y, xv.w, hqacc[1][3]);
        }
        __syncthreads();
    }
    // write hq (no bias; bh applied downstream)
    #pragma unroll
    for (int j = 0; j < 2; j++) {
        int m = 2 * td + j;
        float4 r; r.x = hqacc[j][0]; r.y = hqacc[j][1]; r.z = hqacc[j][2]; r.w = hqacc[j][3];
        *(float4*)&hq_out[((size_t)b * MID + m) * HW + hw0 + 4 * tx] = r;
    }
    // ke: bias + relu, park in smem (overlay of sWk — safe after loop-end sync)
    #pragma unroll
    for (int j = 0; j < 8; j++) {
        int d = 8 * td + j;
        float bsv = g_bke[d];
        float4 r;
        r.x = fmaxf(keacc[j][0] + bsv, 0.f); r.y = fmaxf(keacc[j][1] + bsv, 0.f);
        r.z = fmaxf(keacc[j][2] + bsv, 0.f); r.w = fmaxf(keacc[j][3] + bsv, 0.f);
        *(float4*)&sKE[d * 64 + 4 * tx] = r;
    }
    // stage W1k into sX overlay
    for (int k = tid; k < 1024; k += 256) {
        int c = k >> 3, q = k & 7;
        *(float4*)&sW1k[c * 32 + q * 4] = *(const float4*)&g_W1kt[c * 32 + q * 4];
    }
    __syncthreads();
    float hkacc[2][4];
    #pragma unroll
    for (int j = 0; j < 2; j++)
        #pragma unroll
        for (int i = 0; i < 4; i++) hkacc[j][i] = 0.f;
    #pragma unroll 4
    for (int c = 0; c < 128; c++) {
        float4 hv = *(const float4*)&sKE[c * 64 + 4 * tx];
        float2 w = *(const float2*)&sW1k[c * 32 + 2 * td];
        hkacc[0][0] = fmaf(w.x, hv.x, hkacc[0][0]); hkacc[0][1] = fmaf(w.x, hv.y, hkacc[0][1]);
        hkacc[0][2] = fmaf(w.x, hv.z, hkacc[0][2]); hkacc[0][3] = fmaf(w.x, hv.w, hkacc[0][3]);
        hkacc[1][0] = fmaf(w.y, hv.x, hkacc[1][0]); hkacc[1][1] = fmaf(w.y, hv.y, hkacc[1][1]);
        hkacc[1][2] = fmaf(w.y, hv.z, hkacc[1][2]); hkacc[1][3] = fmaf(w.y, hv.w, hkacc[1][3]);
    }
    #pragma unroll
    for (int j = 0; j < 2; j++) {
        int m = 2 * td + j;
        float4 r; r.x = hkacc[j][0]; r.y = hkacc[j][1]; r.z = hkacc[j][2]; r.w = hkacc[j][3];
        *(float4*)&hk_out[((size_t)b * MID + m) * HW + hw0 + 4 * tx] = r;
    }
}

// ---------------- pointwise-conv GEMM (Wv only): 128 threads, 8 d x 4 px ----------------
template<int DTILE, bool RELU>
__global__ void __launch_bounds__(128) pw_conv_kernel(
    const float* __restrict__ X, const float* __restrict__ Wt,
    const float* __restrict__ bias, float* __restrict__ Y, int Dtot)
{
    constexpr int PX = 64;
    constexpr int CCH = 64;
    constexpr int DN = DTILE / 8;
    __shared__ float sX[CCH * PX];
    __shared__ float sW[CCH * DTILE];
    const int b   = blockIdx.z;
    const int hw0 = blockIdx.x * PX;
    const int d0  = blockIdx.y * DTILE;
    const int tid = threadIdx.x;
    const int tx  = tid & 15;
    const int td  = tid >> 4;
    float acc[DN][4];
    #pragma unroll
    for (int j = 0; j < DN; j++)
        #pragma unroll
        for (int i = 0; i < 4; i++) acc[j][i] = 0.f;
    const float* Xb = X + (size_t)b * CC_IN * HW;
    for (int cc = 0; cc < CC_IN; cc += CCH) {
        for (int k = tid; k < CCH * PX / 4; k += 128) {
            int c = k >> 4, q = k & 15;
            *(float4*)&sX[c * 64 + q * 4] = *(const float4*)&Xb[(size_t)(cc + c) * HW + hw0 + q * 4];
        }
        for (int k = tid; k < CCH * DTILE / 4; k += 128) {
            int c = k / (DTILE / 4), q = k % (DTILE / 4);
            *(float4*)&sW[c * DTILE + q * 4] = *(const float4*)&Wt[(size_t)(cc + c) * Dtot + d0 + q * 4];
        }
        __syncthreads();
        #pragma unroll 4
        for (int c = 0; c < CCH; c++) {
            float4 xv = *(const float4*)&sX[c * 64 + 4 * tx];
            float4 w0 = *(const float4*)&sW[c * DTILE + DN * td];
            acc[0][0] = fmaf(w0.x, xv.x, acc[0][0]); acc[0][1] = fmaf(w0.x, xv.y, acc[0][1]);
            acc[0][2] = fmaf(w0.x, xv.z, acc[0][2]); acc[0][3] = fmaf(w0.x, xv.w, acc[0][3]);
            acc[1][0] = fmaf(w0.y, xv.x, acc[1][0]); acc[1][1] = fmaf(w0.y, xv.y, acc[1][1]);
            acc[1][2] = fmaf(w0.y, xv.z, acc[1][2]); acc[1][3] = fmaf(w0.y, xv.w, acc[1][3]);
            acc[2][0] = fmaf(w0.z, xv.x, acc[2][0]); acc[2][1] = fmaf(w0.z, xv.y, acc[2][1]);
            acc[2][2] = fmaf(w0.z, xv.z, acc[2][2]); acc[2][3] = fmaf(w0.z, xv.w, acc[2][3]);
            acc[3][0] = fmaf(w0.w, xv.x, acc[3][0]); acc[3][1] = fmaf(w0.w, xv.y, acc[3][1]);
            acc[3][2] = fmaf(w0.w, xv.z, acc[3][2]); acc[3][3] = fmaf(w0.w, xv.w, acc[3][3]);
            if (DN == 8) {
                float4 w1 = *(const float4*)&sW[c * DTILE + DN * td + 4];
                acc[4][0] = fmaf(w1.x, xv.x, acc[4][0]); acc[4][1] = fmaf(w1.x, xv.y, acc[4][1]);
                acc[4][2] = fmaf(w1.x, xv.z, acc[4][2]); acc[4][3] = fmaf(w1.x, xv.w, acc[4][3]);
                acc[5][0] = fmaf(w1.y, xv.x, acc[5][0]); acc[5][1] = fmaf(w1.y, xv.y, acc[5][1]);
                acc[5][2] = fmaf(w1.y, xv.z, acc[5][2]); acc[5][3] = fmaf(w1.y, xv.w, acc[5][3]);
                acc[6][0] = fmaf(w1.z, xv.x, acc[6][0]); acc[6][1] = fmaf(w1.z, xv.y, acc[6][1]);
                acc[6][2] = fmaf(w1.z, xv.z, acc[6][2]); acc[6][3] = fmaf(w1.z, xv.w, acc[6][3]);
                acc[7][0] = fmaf(w1.w, xv.x, acc[7][0]); acc[7][1] = fmaf(w1.w, xv.y, acc[7][1]);
                acc[7][2] = fmaf(w1.w, xv.z, acc[7][2]); acc[7][3] = fmaf(w1.w, xv.w, acc[7][3]);
            }
        }
        __syncthreads();
    }
    #pragma unroll
    for (int j = 0; j < DN; j++) {
        int d = d0 + td * DN + j;
        float bsv = bias ? bias[d] : 0.f;
        float4 r;
        r.x = acc[j][0] + bsv; r.y = acc[j][1] + bsv;
        r.z = acc[j][2] + bsv; r.w = acc[j][3] + bsv;
        if (RELU) {
            r.x = fmaxf(r.x, 0.f); r.y = fmaxf(r.y, 0.f);
            r.z = fmaxf(r.z, 0.f); r.w = fmaxf(r.w, 0.f);
        }
        *(float4*)&Y[((size_t)b * Dtot + d) * HW + hw0 + 4 * tx] = r;
    }
}

// ---------------- fused GroupNorm stats: Sh + Gram M directly from hq/hk ----------------
__global__ void fused_stats_kernel(const float* __restrict__ hq, const float* __restrict__ hk,
                                   const float* __restrict__ bh,
                                   float* __restrict__ M, float* __restrict__ Sh)
{
    __shared__ float s_hq[32 * 112];
    __shared__ float s_hk[32 * 224];
    __shared__ float sBH[32];
    __shared__ float sSh[32];
    __shared__ float sM[1024];
    const int b  = blockIdx.y;
    const int y0 = blockIdx.x * 2;
    const int tid = threadIdx.x;
    if (tid < 32) { sBH[tid] = bh[tid]; sSh[tid] = 0.f; }
    for (int k = tid; k < 1024; k += 256) sM[k] = 0.f;
    for (int k = tid; k < 32 * 112; k += 256) {
        int m = k / 112, s = k % 112, r = s / 56, x = s % 56;
        s_hq[k] = hq[((size_t)b * MID + m) * HW + (y0 + r) * WW + x];
    }
    for (int k = tid; k < 32 * 224; k += 256) {
        int m = k / 224, s = k % 224, rr = s / 56, x = s % 56;
        int yy = y0 - 1 + rr;
        s_hk[k] = (yy >= 0 && yy < HH) ? hk[((size_t)b * MID + m) * HW + yy * WW + x] : 0.f;
    }
    __syncthreads();
    {
        int m = tid & 31, ch = tid >> 5;
        float s = 0.f;
        float base = sBH[m];
        for (int px = ch * 14; px < ch * 14 + 14; px++) {
            int r = px / 56, x = px % 56;
            float hqv = s_hq[m * 112 + px] + base;
            #pragma unroll
            for (int p = 0; p < 9; p++) {
                int di = p / 3, dj = p % 3;
                int xx = x + dj - 1;
                float hkv = (xx >= 0 && xx < WW) ? s_hk[m * 224 + (r + di) * 56 + xx] : 0.f;
                s += fmaxf(hqv + hkv, 0.f);
            }
        }
        atomicAdd(&sSh[m], s);
    }
    {
        int combo = tid & 63;
        int it = combo & 7, jt = combo >> 3;
        int pg = tid >> 6;
        float accM[4][4];
        #pragma unroll
        for (int a = 0; a < 4; a++)
            #pragma unroll
            for (int c = 0; c < 4; c++) accM[a][c] = 0.f;
        for (int px = pg * 28; px < pg * 28 + 28; px++) {
            int r = px / 56, x = px % 56;
            for (int p = 0; p < 9; p++) {
                int di = p / 3, dj = p % 3;
                int xx = x + dj - 1;
                bool in = (xx >= 0 && xx < WW);
                float hi[4], hj[4];
                #pragma unroll
                for (int a = 0; a < 4; a++) {
                    int m = it * 4 + a;
                    float hkv = in ? s_hk[m * 224 + (r + di) * 56 + xx] : 0.f;
                    hi[a] = fmaxf(s_hq[m * 112 + px] + hkv + sBH[m], 0.f);
                }
                #pragma unroll
                for (int c = 0; c < 4; c++) {
                    int m = jt * 4 + c;
                    float hkv = in ? s_hk[m * 224 + (r + di) * 56 + xx] : 0.f;
                    hj[c] = fmaxf(s_hq[m * 112 + px] + hkv + sBH[m], 0.f);
                }
                #pragma unroll
                for (int a = 0; a < 4; a++)
                    #pragma unroll
                    for (int c = 0; c < 4; c++) accM[a][c] = fmaf(hi[a], hj[c], accM[a][c]);
            }
        }
        #pragma unroll
        for (int a = 0; a < 4; a++)
            #pragma unroll
            for (int c = 0; c < 4; c++)
                atomicAdd(&sM[(it * 4 + a) * 32 + jt * 4 + c], accM[a][c]);
    }
    __syncthreads();
    if (tid < 32) atomicAdd(&Sh[b * 32 + tid], sSh[tid]);
    for (int k = tid; k < 1024; k += 256) atomicAdd(&M[b * 1024 + k], sM[k]);
}

// ---------------- GroupNorm stats via quadratic forms ----------------
__global__ void stats_kernel(const float* __restrict__ W2, const float* __restrict__ b2,
                             const float* __restrict__ M, const float* __restrict__ Sh,
                             float* __restrict__ mu, float* __restrict__ rinv)
{
    int b = blockIdx.x, o = threadIdx.x;
    __shared__ float sM[1024], sSh[32];
    for (int k = o; k < 1024; k += 128) sM[k] = M[b * 1024 + k];
    if (o < 32) sSh[o] = Sh[b * 32 + o];
    __syncthreads();
    float S1 = 0.f, S2 = 0.f;
    const float NPf = (float)NPQ;
    for (int g = 0; g < GCN; g++) {
        int og = o * GCN + g;
        float w[32];
        #pragma unroll
        for (int m = 0; m < 32; m++) w[m] = W2[og * 32 + m];
        float d1 = 0.f;
        #pragma unroll
        for (int m = 0; m < 32; m++) d1 = fmaf(w[m], sSh[m], d1);
        float q = 0.f;
        for (int i2 = 0; i2 < 32; i2++) {
            float ti = 0.f;
            #pragma unroll
            for (int j = 0; j < 32; j++) ti = fmaf(sM[i2 * 32 + j], w[j], ti);
            q = fmaf(w[i2], ti, q);
        }
        float bbv = b2[og];
        S1 += d1 + bbv * NPf;
        S2 += q + 2.f * bbv * d1 + bbv * bbv * NPf;
    }
    const float N = (float)(GCN * NPQ);
    float m_ = S1 / N;
    float var = S2 / N - m_ * m_;
    mu[b * COUT + o]   = m_;
    rinv[b * COUT + o] = rsqrtf(var + EPS);
}

// ---------------- main fused kernel: 64-cout split, 128 threads, 4o x 4px per thread ----------------
// grid (7, 14, B*2): z = b*2 + half. 8x4 px tile, 64 couts per block.
// smem: sH 9216 | sV 64*62=3968 | sWt 32*68=2176 | sBH 32 = 15392 fl = 61568 B -> 3 blocks/SM
__global__ void __launch_bounds__(128) main_kernel(
    const float* __restrict__ hq, const float* __restrict__ hk,
    const float* __restrict__ v,
    const float* __restrict__ W2t, const float* __restrict__ b2,
    const float* __restrict__ gng, const float* __restrict__ gnb,
    const float* __restrict__ mu, const float* __restrict__ rinv,
    const float* __restrict__ bh, float* __restrict__ out)
{
    extern __shared__ float smem[];
    float* sH  = smem;                 // 9216
    float* sV  = smem + 9216;          // 3968
    float* sWt = smem + 13184;         // 2176
    float* sBH = smem + 15360;         // 32
    float* s_hq = sV;                  // staging overlay (1024)
    float* s_hk = sV + 1024;           // staging overlay (1920; fits in sV+sWt region)
    const int bz  = blockIdx.z;
    const int b   = bz >> 1;
    const int ob0 = (bz & 1) * 64;     // cout base for this block
    const int x0  = blockIdx.x * 8;
    const int y0  = blockIdx.y * 4;
    const int tid = threadIdx.x;
    const int tq  = tid & 7;
    const int to  = tid >> 3;          // 0..15, owns 4 couts
    const int ly  = tq >> 1;
    const int lx0 = (tq & 1) * 4;

    if (tid < 32) sBH[tid] = bh[tid];
    for (int k = tid; k < 1024; k += 128) {
        int m = k >> 5, px = k & 31, lyy = px >> 3, lxx = px & 7;
        s_hq[k] = hq[((size_t)b * MID + m) * HW + (y0 + lyy) * WW + x0 + lxx];
    }
    for (int k = tid; k < 1920; k += 128) {
        int m = k / 60, s = k % 60, yy = s / 10, xx = s % 10;
        int gy = y0 - 1 + yy, gx = x0 - 1 + xx;
        s_hk[k] = (gy >= 0 && gy < HH && gx >= 0 && gx < WW)
                  ? hk[((size_t)b * MID + m) * HW + gy * WW + gx] : 0.f;
    }
    __syncthreads();
    for (int k = tid; k < 9216; k += 128) {
        int p = k >> 10, m = (k >> 5) & 31, px = k & 31;
        int lyy = px >> 3, lxx = px & 7;
        int di = p / 3, dj = p % 3;
        float val = s_hq[m * 32 + px] + s_hk[m * 60 + (lyy + di) * 10 + (lxx + dj)] + sBH[m];
        sH[k] = fmaxf(val, 0.f);
    }

    float acc[4][4];
    #pragma unroll
    for (int oo = 0; oo < 4; oo++)
        #pragma unroll
        for (int i = 0; i < 4; i++) acc[oo][i] = 0.f;

    const float* vb = v + (size_t)b * OG * HW;
    for (int g = 0; g < GCN; g++) {
        __syncthreads();
        for (int k = tid; k < 64 * 60; k += 128) {
            int o = k / 60, s = k % 60, yy = s / 10, xx = s % 10;
            int gy = y0 - 1 + yy, gx = x0 - 1 + xx;
            float val = 0.f;
            if (gy >= 0 && gy < HH && gx >= 0 && gx < WW)
                val = vb[(size_t)((ob0 + o) * GCN + g) * HW + gy * WW + gx];
            sV[o * 62 + s] = val;
        }
        for (int k = tid; k < 2048; k += 128) {
            int m = k >> 6, o = k & 63;
            sWt[m * 68 + o] = W2t[(g * MID + m) * COUT + ob0 + o];
        }
        __syncthreads();

        float c1r[4], c0r[4];
        #pragma unroll
        for (int oo = 0; oo < 4; oo++) {
            int o = ob0 + to * 4 + oo;
            int og = o * GCN + g;
            float c1 = rinv[b * COUT + o] * gng[og];
            c1r[oo] = c1;
            c0r[oo] = c1 * b2[og] + gnb[og] - mu[b * COUT + o] * c1;
        }

        #pragma unroll
        for (int sweep = 0; sweep < 3; sweep++) {
            float aacc[3][4][4];
            #pragma unroll
            for (int pp = 0; pp < 3; pp++)
                #pragma unroll
                for (int oo = 0; oo < 4; oo++)
                    #pragma unroll
                    for (int i = 0; i < 4; i++) aacc[pp][oo][i] = 0.f;
            #pragma unroll 8
            for (int m = 0; m < 32; m++) {
                float4 w = *(const float4*)&sWt[m * 68 + 4 * to];
                #pragma unroll
                for (int pp = 0; pp < 3; pp++) {
                    float4 hv = *(const float4*)&sH[((sweep * 3 + pp) << 10) + (m << 5) + 4 * tq];
                    float* a0 = &aacc[pp][0][0];
                    a0[0]  = fmaf(w.x, hv.x, a0[0]);  a0[1]  = fmaf(w.x, hv.y, a0[1]);
                    a0[2]  = fmaf(w.x, hv.z, a0[2]);  a0[3]  = fmaf(w.x, hv.w, a0[3]);
                    a0[4]  = fmaf(w.y, hv.x, a0[4]);  a0[5]  = fmaf(w.y, hv.y, a0[5]);
                    a0[6]  = fmaf(w.y, hv.z, a0[6]);  a0[7]  = fmaf(w.y, hv.w, a0[7]);
                    a0[8]  = fmaf(w.z, hv.x, a0[8]);  a0[9]  = fmaf(w.z, hv.y, a0[9]);
                    a0[10] = fmaf(w.z, hv.z, a0[10]); a0[11] = fmaf(w.z, hv.w, a0[11]);
                    a0[12] = fmaf(w.w, hv.x, a0[12]); a0[13] = fmaf(w.w, hv.y, a0[13]);
                    a0[14] = fmaf(w.w, hv.z, a0[14]); a0[15] = fmaf(w.w, hv.w, a0[15]);
                }
            }
            #pragma unroll
            for (int pp = 0; pp < 3; pp++) {
                #pragma unroll
                for (int oo = 0; oo < 4; oo++) {
                    float c1 = c1r[oo], c0 = c0r[oo];
                    int ol = to * 4 + oo;
                    #pragma unroll
                    for (int i = 0; i < 4; i++) {
                        float Vv = sV[ol * 62 + (ly + sweep) * 10 + (lx0 + i + pp)];
                        float t = fmaf(c1, aacc[pp][oo][i], c0);
                        acc[oo][i] = fmaf(t, Vv, acc[oo][i]);
                    }
                }
            }
        }
    }
    #pragma unroll
    for (int oo = 0; oo < 4; oo++) {
        float4 r;
        r.x = acc[oo][0]; r.y = acc[oo][1]; r.z = acc[oo][2]; r.w = acc[oo][3];
        *(float4*)&out[((size_t)b * COUT + ob0 + to * 4 + oo) * HW + (y0 + ly) * WW + x0 + lx0] = r;
    }
}

// ---------------- launch ----------------
extern "C" void kernel_launch(void* const* d_in, const int* in_sizes, int n_in,
                              void* d_out, int out_size)
{
    const float* x     = (const float*)d_in[0];
    const float* Wk    = (const float*)d_in[1];
    const float* bn1g  = (const float*)d_in[2];
    const float* bn1b  = (const float*)d_in[3];
    const float* bn1m  = (const float*)d_in[4];
    const float* bn1v  = (const float*)d_in[5];
    const float* W1    = (const float*)d_in[6];
    const float* b1    = (const float*)d_in[7];
    const float* bn2g  = (const float*)d_in[8];
    const float* bn2b  = (const float*)d_in[9];
    const float* bn2m  = (const float*)d_in[10];
    const float* bn2v  = (const float*)d_in[11];
    const float* W2    = (const float*)d_in[12];
    const float* b2    = (const float*)d_in[13];
    const float* gng   = (const float*)d_in[14];
    const float* gnb   = (const float*)d_in[15];
    const float* Wv    = (const float*)d_in[16];
    const float* bnvg  = (const float*)d_in[17];
    const float* bnvb  = (const float*)d_in[18];
    const float* bnvm  = (const float*)d_in[19];
    const float* bnvv  = (const float*)d_in[20];
    float* out = (float*)d_out;

    float *vv, *hq, *hk, *pM, *pSh, *pmu, *pri;
    float *pWvt, *pW2t, *pbv, *pbh;
    cudaGetSymbolAddress((void**)&vv,    g_v);
    cudaGetSymbolAddress((void**)&hq,    g_hq);
    cudaGetSymbolAddress((void**)&hk,    g_hk);
    cudaGetSymbolAddress((void**)&pM,    g_M);
    cudaGetSymbolAddress((void**)&pSh,   g_Sh);
    cudaGetSymbolAddress((void**)&pmu,   g_mu);
    cudaGetSymbolAddress((void**)&pri,   g_ri);
    cudaGetSymbolAddress((void**)&pWvt,  g_Wvt);
    cudaGetSymbolAddress((void**)&pW2t,  g_W2t);
    cudaGetSymbolAddress((void**)&pbv,   g_bv);
    cudaGetSymbolAddress((void**)&pbh,   g_bh);

    static bool attr_set = false;
    if (!attr_set) {
        cudaFuncSetAttribute(main_kernel,  cudaFuncAttributeMaxDynamicSharedMemorySize, 61568);
        cudaFuncSetAttribute(front_kernel, cudaFuncAttributeMaxDynamicSharedMemorySize, 57344);
        attr_set = true;
    }

    fold_kernel<<<(111392 + 255) / 256, 256>>>(Wk, bn1g, bn1b, bn1m, bn1v,
                                               W1, b1, bn2g, bn2b, bn2m, bn2v,
                                               W2, Wv, bnvg, bnvb, bnvm, bnvv);
    front_kernel<<<dim3(49, BB), 256, 57344>>>(x, hq, hk);
    pw_conv_kernel<64, false><<<dim3(49, 8, BB), 128>>>(x, pWvt, pbv, vv, OG);
    fused_stats_kernel<<<dim3(28, BB), 256>>>(hq, hk, pbh, pM, pSh);
    stats_kernel<<<BB, 128>>>(W2, b2, pM, pSh, pmu, pri);
    main_kernel<<<dim3(7, 14, BB * 2), 128, 61568>>>(hq, hk, vv, pW2t, b2, gng, gnb,
                                                     pmu, pri, pbh, out);
}

// round 7
// speedup vs baseline: 2.6647x; 1.2588x over previous
#include <cuda_runtime.h>
#include <cuda_bf16.h>
#include <math.h>

#define BB 4
#define CC_IN 128
#define HH 56
#define WW 56
#define HW 3136
#define MID 32
#define OG 512
#define COUT 128
#define GCN 4
#define K2 9
#define NPQ 28224
#define EPS 1e-5f

// ---------------- device scratch ----------------
__device__ float g_v [BB * OG * HW];
__device__ float g_hq[BB * MID * HW];
__device__ float g_hk[BB * MID * HW];
__device__ float g_Wkt [CC_IN * CC_IN];      // [c][d]
__device__ float g_W1qt[CC_IN * MID];        // [c][m]
__device__ float g_W1kt[CC_IN * MID];        // [c][m]
__device__ float g_Wvt [CC_IN * OG];         // [c][o]
__device__ float g_W2t [GCN * MID * COUT];   // [g][m][o]
__device__ float g_bke[CC_IN];
__device__ float g_bh [MID];
__device__ float g_bv [OG];
__device__ float g_M  [BB * MID * MID];
__device__ float g_Sh [BB * MID];
__device__ float g_mu [BB * COUT];
__device__ float g_ri [BB * COUT];

// Fold BN affines into (transposed) weights + zero M/Sh accumulators.
__global__ void fold_kernel(
    const float* __restrict__ Wk,
    const float* __restrict__ bn1g, const float* __restrict__ bn1b,
    const float* __restrict__ bn1m, const float* __restrict__ bn1v,
    const float* __restrict__ W1,  const float* __restrict__ b1,
    const float* __restrict__ bn2g, const float* __restrict__ bn2b,
    const float* __restrict__ bn2m, const float* __restrict__ bn2v,
    const float* __restrict__ W2,
    const float* __restrict__ Wv,
    const float* __restrict__ bnvg, const float* __restrict__ bnvb,
    const float* __restrict__ bnvm, const float* __restrict__ bnvv)
{
    int i = blockIdx.x * blockDim.x + threadIdx.x;
    if (i < 16384) {
        int d = i >> 7, c = i & 127;
        float s = bn1g[d] * rsqrtf(bn1v[d] + EPS);
        g_Wkt[c * 128 + d] = Wk[d * 128 + c] * s;
    } else if (i < 20480) {
        int j = i - 16384; int m = j >> 7, c = j & 127;
        float s = bn2g[m] * rsqrtf(bn2v[m] + EPS);
        g_W1qt[c * MID + m] = W1[m * 256 + c] * s;
    } else if (i < 24576) {
        int j = i - 20480; int m = j >> 7, c = j & 127;
        float s = bn2g[m] * rsqrtf(bn2v[m] + EPS);
        g_W1kt[c * MID + m] = W1[m * 256 + 128 + c] * s;
    } else if (i < 90112) {
        int j = i - 24576; int o = j >> 7, c = j & 127;
        float s = bnvg[o] * rsqrtf(bnvv[o] + EPS);
        g_Wvt[c * OG + o] = Wv[o * 128 + c] * s;
    } else if (i < 106496) {
        int j = i - 90112; int o = j & 127, t = j >> 7;
        int g = t >> 5, m = t & 31;
        g_W2t[(g * MID + m) * COUT + o] = W2[(o * GCN + g) * MID + m];
    } else if (i < 106624) {
        int d = i - 106496;
        float s = bn1g[d] * rsqrtf(bn1v[d] + EPS);
        g_bke[d] = bn1b[d] - bn1m[d] * s;
    } else if (i < 106656) {
        int m = i - 106624;
        float s = bn2g[m] * rsqrtf(bn2v[m] + EPS);
        g_bh[m] = s * b1[m] + bn2b[m] - bn2m[m] * s;
    } else if (i < 107168) {
        int o = i - 106656;
        float s = bnvg[o] * rsqrtf(bnvv[o] + EPS);
        g_bv[o] = bnvb[o] - bnvm[o] * s;
    } else if (i < 111264) {
        g_M[i - 107168] = 0.f;
    } else if (i < 111392) {
        g_Sh[i - 111264] = 0.f;
    }
}

// ---------------- front kernel: ke (regs/smem only) + hq + hk in one pass ----------------
__global__ void __launch_bounds__(256) front_kernel(
    const float* __restrict__ X,
    float* __restrict__ hq_out, float* __restrict__ hk_out)
{
    extern __shared__ float fsm[];
    float* sX   = fsm;            // 4096
    float* sWk  = fsm + 4096;     // 8192
    float* sW1q = fsm + 12288;    // 2048
    float* sW1k = fsm;            // overlay of sX
    float* sKE  = fsm + 4096;     // overlay of sWk
    const int b   = blockIdx.y;
    const int hw0 = blockIdx.x * 64;
    const int tid = threadIdx.x;
    const int tx  = tid & 15;
    const int td  = tid >> 4;

    float keacc[8][4];
    float hqacc[2][4];
    #pragma unroll
    for (int j = 0; j < 8; j++)
        #pragma unroll
        for (int i = 0; i < 4; i++) keacc[j][i] = 0.f;
    #pragma unroll
    for (int j = 0; j < 2; j++)
        #pragma unroll
        for (int i = 0; i < 4; i++) hqacc[j][i] = 0.f;

    const float* Xb = X + (size_t)b * CC_IN * HW;
    for (int cc = 0; cc < 128; cc += 64) {
        for (int k = tid; k < 1024; k += 256) {
            int c = k >> 4, q = k & 15;
            *(float4*)&sX[c * 64 + q * 4] = *(const float4*)&Xb[(size_t)(cc + c) * HW + hw0 + q * 4];
        }
        for (int k = tid; k < 2048; k += 256) {
            int c = k >> 5, q = k & 31;
            *(float4*)&sWk[c * 128 + q * 4] = *(const float4*)&g_Wkt[(cc + c) * 128 + q * 4];
        }
        for (int k = tid; k < 512; k += 256) {
            int c = k >> 3, q = k & 7;
            *(float4*)&sW1q[c * 32 + q * 4] = *(const float4*)&g_W1qt[(cc + c) * 32 + q * 4];
        }
        __syncthreads();
        #pragma unroll 4
        for (int c = 0; c < 64; c++) {
            float4 xv = *(const float4*)&sX[c * 64 + 4 * tx];
            float4 w0 = *(const float4*)&sWk[c * 128 + 8 * td];
            float4 w1 = *(const float4*)&sWk[c * 128 + 8 * td + 4];
            keacc[0][0] = fmaf(w0.x, xv.x, keacc[0][0]); keacc[0][1] = fmaf(w0.x, xv.y, keacc[0][1]);
            keacc[0][2] = fmaf(w0.x, xv.z, keacc[0][2]); keacc[0][3] = fmaf(w0.x, xv.w, keacc[0][3]);
            keacc[1][0] = fmaf(w0.y, xv.x, keacc[1][0]); keacc[1][1] = fmaf(w0.y, xv.y, keacc[1][1]);
            keacc[1][2] = fmaf(w0.y, xv.z, keacc[1][2]); keacc[1][3] = fmaf(w0.y, xv.w, keacc[1][3]);
            keacc[2][0] = fmaf(w0.z, xv.x, keacc[2][0]); keacc[2][1] = fmaf(w0.z, xv.y, keacc[2][1]);
            keacc[2][2] = fmaf(w0.z, xv.z, keacc[2][2]); keacc[2][3] = fmaf(w0.z, xv.w, keacc[2][3]);
            keacc[3][0] = fmaf(w0.w, xv.x, keacc[3][0]); keacc[3][1] = fmaf(w0.w, xv.y, keacc[3][1]);
            keacc[3][2] = fmaf(w0.w, xv.z, keacc[3][2]); keacc[3][3] = fmaf(w0.w, xv.w, keacc[3][3]);
            keacc[4][0] = fmaf(w1.x, xv.x, keacc[4][0]); keacc[4][1] = fmaf(w1.x, xv.y, keacc[4][1]);
            keacc[4][2] = fmaf(w1.x, xv.z, keacc[4][2]); keacc[4][3] = fmaf(w1.x, xv.w, keacc[4][3]);
            keacc[5][0] = fmaf(w1.y, xv.x, keacc[5][0]); keacc[5][1] = fmaf(w1.y, xv.y, keacc[5][1]);
            keacc[5][2] = fmaf(w1.y, xv.z, keacc[5][2]); keacc[5][3] = fmaf(w1.y, xv.w, keacc[5][3]);
            keacc[6][0] = fmaf(w1.z, xv.x, keacc[6][0]); keacc[6][1] = fmaf(w1.z, xv.y, keacc[6][1]);
            keacc[6][2] = fmaf(w1.z, xv.z, keacc[6][2]); keacc[6][3] = fmaf(w1.z, xv.w, keacc[6][3]);
            keacc[7][0] = fmaf(w1.w, xv.x, keacc[7][0]); keacc[7][1] = fmaf(w1.w, xv.y, keacc[7][1]);
            keacc[7][2] = fmaf(w1.w, xv.z, keacc[7][2]); keacc[7][3] = fmaf(w1.w, xv.w, keacc[7][3]);
            float2 wq = *(const float2*)&sW1q[c * 32 + 2 * td];
            hqacc[0][0] = fmaf(wq.x, xv.x, hqacc[0][0]); hqacc[0][1] = fmaf(wq.x, xv.y, hqacc[0][1]);
            hqacc[0][2] = fmaf(wq.x, xv.z, hqacc[0][2]); hqacc[0][3] = fmaf(wq.x, xv.w, hqacc[0][3]);
            hqacc[1][0] = fmaf(wq.y, xv.x, hqacc[1][0]); hqacc[1][1] = fmaf(wq.y, xv.y, hqacc[1][1]);
            hqacc[1][2] = fmaf(wq.y, xv.z, hqacc[1][2]); hqacc[1][3] = fmaf(wq.y, xv.w, hqacc[1][3]);
        }
        __syncthreads();
    }
    #pragma unroll
    for (int j = 0; j < 2; j++) {
        int m = 2 * td + j;
        float4 r; r.x = hqacc[j][0]; r.y = hqacc[j][1]; r.z = hqacc[j][2]; r.w = hqacc[j][3];
        *(float4*)&hq_out[((size_t)b * MID + m) * HW + hw0 + 4 * tx] = r;
    }
    #pragma unroll
    for (int j = 0; j < 8; j++) {
        int d = 8 * td + j;
        float bsv = g_bke[d];
        float4 r;
        r.x = fmaxf(keacc[j][0] + bsv, 0.f); r.y = fmaxf(keacc[j][1] + bsv, 0.f);
        r.z = fmaxf(keacc[j][2] + bsv, 0.f); r.w = fmaxf(keacc[j][3] + bsv, 0.f);
        *(float4*)&sKE[d * 64 + 4 * tx] = r;
    }
    for (int k = tid; k < 1024; k += 256) {
        int c = k >> 3, q = k & 7;
        *(float4*)&sW1k[c * 32 + q * 4] = *(const float4*)&g_W1kt[c * 32 + q * 4];
    }
    __syncthreads();
    float hkacc[2][4];
    #pragma unroll
    for (int j = 0; j < 2; j++)
        #pragma unroll
        for (int i = 0; i < 4; i++) hkacc[j][i] = 0.f;
    #pragma unroll 4
    for (int c = 0; c < 128; c++) {
        float4 hv = *(const float4*)&sKE[c * 64 + 4 * tx];
        float2 w = *(const float2*)&sW1k[c * 32 + 2 * td];
        hkacc[0][0] = fmaf(w.x, hv.x, hkacc[0][0]); hkacc[0][1] = fmaf(w.x, hv.y, hkacc[0][1]);
        hkacc[0][2] = fmaf(w.x, hv.z, hkacc[0][2]); hkacc[0][3] = fmaf(w.x, hv.w, hkacc[0][3]);
        hkacc[1][0] = fmaf(w.y, hv.x, hkacc[1][0]); hkacc[1][1] = fmaf(w.y, hv.y, hkacc[1][1]);
        hkacc[1][2] = fmaf(w.y, hv.z, hkacc[1][2]); hkacc[1][3] = fmaf(w.y, hv.w, hkacc[1][3]);
    }
    #pragma unroll
    for (int j = 0; j < 2; j++) {
        int m = 2 * td + j;
        float4 r; r.x = hkacc[j][0]; r.y = hkacc[j][1]; r.z = hkacc[j][2]; r.w = hkacc[j][3];
        *(float4*)&hk_out[((size_t)b * MID + m) * HW + hw0 + 4 * tx] = r;
    }
}

// ---------------- pointwise-conv GEMM (Wv): 128 threads, 8 d x 4 px ----------------
template<int DTILE, bool RELU>
__global__ void __launch_bounds__(128) pw_conv_kernel(
    const float* __restrict__ X, const float* __restrict__ Wt,
    const float* __restrict__ bias, float* __restrict__ Y, int Dtot)
{
    constexpr int PX = 64;
    constexpr int CCH = 64;
    constexpr int DN = DTILE / 8;
    __shared__ float sX[CCH * PX];
    __shared__ float sW[CCH * DTILE];
    const int b   = blockIdx.z;
    const int hw0 = blockIdx.x * PX;
    const int d0  = blockIdx.y * DTILE;
    const int tid = threadIdx.x;
    const int tx  = tid & 15;
    const int td  = tid >> 4;
    float acc[DN][4];
    #pragma unroll
    for (int j = 0; j < DN; j++)
        #pragma unroll
        for (int i = 0; i < 4; i++) acc[j][i] = 0.f;
    const float* Xb = X + (size_t)b * CC_IN * HW;
    for (int cc = 0; cc < CC_IN; cc += CCH) {
        for (int k = tid; k < CCH * PX / 4; k += 128) {
            int c = k >> 4, q = k & 15;
            *(float4*)&sX[c * 64 + q * 4] = *(const float4*)&Xb[(size_t)(cc + c) * HW + hw0 + q * 4];
        }
        for (int k = tid; k < CCH * DTILE / 4; k += 128) {
            int c = k / (DTILE / 4), q = k % (DTILE / 4);
            *(float4*)&sW[c * DTILE + q * 4] = *(const float4*)&Wt[(size_t)(cc + c) * Dtot + d0 + q * 4];
        }
        __syncthreads();
        #pragma unroll 4
        for (int c = 0; c < CCH; c++) {
            float4 xv = *(const float4*)&sX[c * 64 + 4 * tx];
            float4 w0 = *(const float4*)&sW[c * DTILE + DN * td];
            acc[0][0] = fmaf(w0.x, xv.x, acc[0][0]); acc[0][1] = fmaf(w0.x, xv.y, acc[0][1]);
            acc[0][2] = fmaf(w0.x, xv.z, acc[0][2]); acc[0][3] = fmaf(w0.x, xv.w, acc[0][3]);
            acc[1][0] = fmaf(w0.y, xv.x, acc[1][0]); acc[1][1] = fmaf(w0.y, xv.y, acc[1][1]);
            acc[1][2] = fmaf(w0.y, xv.z, acc[1][2]); acc[1][3] = fmaf(w0.y, xv.w, acc[1][3]);
            acc[2][0] = fmaf(w0.z, xv.x, acc[2][0]); acc[2][1] = fmaf(w0.z, xv.y, acc[2][1]);
            acc[2][2] = fmaf(w0.z, xv.z, acc[2][2]); acc[2][3] = fmaf(w0.z, xv.w, acc[2][3]);
            acc[3][0] = fmaf(w0.w, xv.x, acc[3][0]); acc[3][1] = fmaf(w0.w, xv.y, acc[3][1]);
            acc[3][2] = fmaf(w0.w, xv.z, acc[3][2]); acc[3][3] = fmaf(w0.w, xv.w, acc[3][3]);
            if (DN == 8) {
                float4 w1 = *(const float4*)&sW[c * DTILE + DN * td + 4];
                acc[4][0] = fmaf(w1.x, xv.x, acc[4][0]); acc[4][1] = fmaf(w1.x, xv.y, acc[4][1]);
                acc[4][2] = fmaf(w1.x, xv.z, acc[4][2]); acc[4][3] = fmaf(w1.x, xv.w, acc[4][3]);
                acc[5][0] = fmaf(w1.y, xv.x, acc[5][0]); acc[5][1] = fmaf(w1.y, xv.y, acc[5][1]);
                acc[5][2] = fmaf(w1.y, xv.z, acc[5][2]); acc[5][3] = fmaf(w1.y, xv.w, acc[5][3]);
                acc[6][0] = fmaf(w1.z, xv.x, acc[6][0]); acc[6][1] = fmaf(w1.z, xv.y, acc[6][1]);
                acc[6][2] = fmaf(w1.z, xv.z, acc[6][2]); acc[6][3] = fmaf(w1.z, xv.w, acc[6][3]);
                acc[7][0] = fmaf(w1.w, xv.x, acc[7][0]); acc[7][1] = fmaf(w1.w, xv.y, acc[7][1]);
                acc[7][2] = fmaf(w1.w, xv.z, acc[7][2]); acc[7][3] = fmaf(w1.w, xv.w, acc[7][3]);
            }
        }
        __syncthreads();
    }
    #pragma unroll
    for (int j = 0; j < DN; j++) {
        int d = d0 + td * DN + j;
        float bsv = bias ? bias[d] : 0.f;
        float4 r;
        r.x = acc[j][0] + bsv; r.y = acc[j][1] + bsv;
        r.z = acc[j][2] + bsv; r.w = acc[j][3] + bsv;
        if (RELU) {
            r.x = fmaxf(r.x, 0.f); r.y = fmaxf(r.y, 0.f);
            r.z = fmaxf(r.z, 0.f); r.w = fmaxf(r.w, 0.f);
        }
        *(float4*)&Y[((size_t)b * Dtot + d) * HW + hw0 + 4 * tx] = r;
    }
}

// ---------------- stats via row-wise SYRK: grid (56 rows, 3 di, B), 256 thr ----------------
// Per block: one image row y, one di. For dj=0..2: build h once into sHp[x][m] (stride 32),
// then full 32x32 SYRK update via 8x8 combos x 4 px-groups with float4 reads.
__global__ void __launch_bounds__(256) stats_gram_kernel(
    const float* __restrict__ hq, const float* __restrict__ hk,
    const float* __restrict__ bh,
    float* __restrict__ M, float* __restrict__ Sh)
{
    __shared__ float s_hq[32 * 56];   // [m][x]
    __shared__ float s_hk[32 * 58];   // [m][x+1], zero-padded x=-1,56
    __shared__ float sHp [56 * 32];   // [x][m]
    __shared__ float sSh [32];
    __shared__ float sM  [1024];
    const int y  = blockIdx.x;
    const int di = blockIdx.y;
    const int b  = blockIdx.z;
    const int tid = threadIdx.x;
    const int mloc = tid & 31;
    if (tid < 32) sSh[tid] = 0.f;
    for (int k = tid; k < 1024; k += 256) sM[k] = 0.f;
    for (int k = tid; k < 1792; k += 256) {
        int m = k / 56, x = k % 56;
        s_hq[m * 56 + x] = hq[((size_t)b * MID + m) * HW + y * WW + x];
    }
    const int yk = y + di - 1;
    const bool rowin = (yk >= 0 && yk < HH);
    for (int k = tid; k < 1856; k += 256) {
        int m = k / 58, xi = k % 58;
        int xp = xi - 1;
        s_hk[k] = (rowin && xp >= 0 && xp < WW)
                 ? hk[((size_t)b * MID + m) * HW + yk * WW + xp] : 0.f;
    }
    const float bhm = bh[mloc];
    float shsum = 0.f;
    const int combo = tid & 63;
    const int it = combo & 7, jt = combo >> 3;
    const int pg = tid >> 6;
    float accM[4][4];
    #pragma unroll
    for (int a = 0; a < 4; a++)
        #pragma unroll
        for (int c = 0; c < 4; c++) accM[a][c] = 0.f;

    for (int dj = 0; dj < 3; dj++) {
        __syncthreads();
        // build: k stride 256 keeps m = tid&31 constant -> private Sh accumulation
        for (int k = tid; k < 1792; k += 256) {
            int x = k >> 5;
            float v = fmaxf(s_hq[mloc * 56 + x] + s_hk[mloc * 58 + x + dj] + bhm, 0.f);
            sHp[k] = v;
            shsum += v;
        }
        __syncthreads();
        #pragma unroll 2
        for (int px = pg * 14; px < pg * 14 + 14; px++) {
            float4 hi = *(const float4*)&sHp[px * 32 + it * 4];
            float4 hj = *(const float4*)&sHp[px * 32 + jt * 4];
            accM[0][0] = fmaf(hi.x, hj.x, accM[0][0]); accM[0][1] = fmaf(hi.x, hj.y, accM[0][1]);
            accM[0][2] = fmaf(hi.x, hj.z, accM[0][2]); accM[0][3] = fmaf(hi.x, hj.w, accM[0][3]);
            accM[1][0] = fmaf(hi.y, hj.x, accM[1][0]); accM[1][1] = fmaf(hi.y, hj.y, accM[1][1]);
            accM[1][2] = fmaf(hi.y, hj.z, accM[1][2]); accM[1][3] = fmaf(hi.y, hj.w, accM[1][3]);
            accM[2][0] = fmaf(hi.z, hj.x, accM[2][0]); accM[2][1] = fmaf(hi.z, hj.y, accM[2][1]);
            accM[2][2] = fmaf(hi.z, hj.z, accM[2][2]); accM[2][3] = fmaf(hi.z, hj.w, accM[2][3]);
            accM[3][0] = fmaf(hi.w, hj.x, accM[3][0]); accM[3][1] = fmaf(hi.w, hj.y, accM[3][1]);
            accM[3][2] = fmaf(hi.w, hj.z, accM[3][2]); accM[3][3] = fmaf(hi.w, hj.w, accM[3][3]);
        }
    }
    atomicAdd(&sSh[mloc], shsum);
    #pragma unroll
    for (int a = 0; a < 4; a++)
        #pragma unroll
        for (int c = 0; c < 4; c++)
            atomicAdd(&sM[(it * 4 + a) * 32 + jt * 4 + c], accM[a][c]);
    __syncthreads();
    if (tid < 32) atomicAdd(&Sh[b * 32 + tid], sSh[tid]);
    for (int k = tid; k < 1024; k += 256) atomicAdd(&M[b * 1024 + k], sM[k]);
}

// ---------------- GroupNorm stats via quadratic forms ----------------
__global__ void stats_kernel(const float* __restrict__ W2, const float* __restrict__ b2,
                             const float* __restrict__ M, const float* __restrict__ Sh,
                             float* __restrict__ mu, float* __restrict__ rinv)
{
    int b = blockIdx.x, o = threadIdx.x;
    __shared__ float sM[1024], sSh[32];
    for (int k = o; k < 1024; k += 128) sM[k] = M[b * 1024 + k];
    if (o < 32) sSh[o] = Sh[b * 32 + o];
    __syncthreads();
    float S1 = 0.f, S2 = 0.f;
    const float NPf = (float)NPQ;
    for (int g = 0; g < GCN; g++) {
        int og = o * GCN + g;
        float w[32];
        #pragma unroll
        for (int m = 0; m < 32; m++) w[m] = W2[og * 32 + m];
        float d1 = 0.f;
        #pragma unroll
        for (int m = 0; m < 32; m++) d1 = fmaf(w[m], sSh[m], d1);
        float q = 0.f;
        for (int i2 = 0; i2 < 32; i2++) {
            float ti = 0.f;
            #pragma unroll
            for (int j = 0; j < 32; j++) ti = fmaf(sM[i2 * 32 + j], w[j], ti);
            q = fmaf(w[i2], ti, q);
        }
        float bbv = b2[og];
        S1 += d1 + bbv * NPf;
        S2 += q + 2.f * bbv * d1 + bbv * bbv * NPf;
    }
    const float N = (float)(GCN * NPQ);
    float m_ = S1 / N;
    float var = S2 / N - m_ * m_;
    mu[b * COUT + o]   = m_;
    rinv[b * COUT + o] = rsqrtf(var + EPS);
}

// ---------------- main fused kernel: 64-cout split, 128 threads, 4o x 4px per thread ----------------
__global__ void __launch_bounds__(128) main_kernel(
    const float* __restrict__ hq, const float* __restrict__ hk,
    const float* __restrict__ v,
    const float* __restrict__ W2t, const float* __restrict__ b2,
    const float* __restrict__ gng, const float* __restrict__ gnb,
    const float* __restrict__ mu, const float* __restrict__ rinv,
    const float* __restrict__ bh, float* __restrict__ out)
{
    extern __shared__ float smem[];
    float* sH  = smem;                 // 9216
    float* sV  = smem + 9216;          // 3968
    float* sWt = smem + 13184;         // 2176
    float* sBH = smem + 15360;         // 32
    float* s_hq = sV;                  // staging overlay (1024)
    float* s_hk = sV + 1024;           // staging overlay (1920)
    const int bz  = blockIdx.z;
    const int b   = bz >> 1;
    const int ob0 = (bz & 1) * 64;
    const int x0  = blockIdx.x * 8;
    const int y0  = blockIdx.y * 4;
    const int tid = threadIdx.x;
    const int tq  = tid & 7;
    const int to  = tid >> 3;
    const int ly  = tq >> 1;
    const int lx0 = (tq & 1) * 4;

    if (tid < 32) sBH[tid] = bh[tid];
    for (int k = tid; k < 1024; k += 128) {
        int m = k >> 5, px = k & 31, lyy = px >> 3, lxx = px & 7;
        s_hq[k] = hq[((size_t)b * MID + m) * HW + (y0 + lyy) * WW + x0 + lxx];
    }
    for (int k = tid; k < 1920; k += 128) {
        int m = k / 60, s = k % 60, yy = s / 10, xx = s % 10;
        int gy = y0 - 1 + yy, gx = x0 - 1 + xx;
        s_hk[k] = (gy >= 0 && gy < HH && gx >= 0 && gx < WW)
                  ? hk[((size_t)b * MID + m) * HW + gy * WW + gx] : 0.f;
    }
    __syncthreads();
    for (int k = tid; k < 9216; k += 128) {
        int p = k >> 10, m = (k >> 5) & 31, px = k & 31;
        int lyy = px >> 3, lxx = px & 7;
        int di = p / 3, dj = p % 3;
        float val = s_hq[m * 32 + px] + s_hk[m * 60 + (lyy + di) * 10 + (lxx + dj)] + sBH[m];
        sH[k] = fmaxf(val, 0.f);
    }

    float acc[4][4];
    #pragma unroll
    for (int oo = 0; oo < 4; oo++)
        #pragma unroll
        for (int i = 0; i < 4; i++) acc[oo][i] = 0.f;

    const float* vb = v + (size_t)b * OG * HW;
    for (int g = 0; g < GCN; g++) {
        __syncthreads();
        for (int k = tid; k < 64 * 60; k += 128) {
            int o = k / 60, s = k % 60, yy = s / 10, xx = s % 10;
            int gy = y0 - 1 + yy, gx = x0 - 1 + xx;
            float val = 0.f;
            if (gy >= 0 && gy < HH && gx >= 0 && gx < WW)
                val = vb[(size_t)((ob0 + o) * GCN + g) * HW + gy * WW + gx];
            sV[o * 62 + s] = val;
        }
        for (int k = tid; k < 2048; k += 128) {
            int m = k >> 6, o = k & 63;
            sWt[m * 68 + o] = W2t[(g * MID + m) * COUT + ob0 + o];
        }
        __syncthreads();

        float c1r[4], c0r[4];
        #pragma unroll
        for (int oo = 0; oo < 4; oo++) {
            int o = ob0 + to * 4 + oo;
            int og = o * GCN + g;
            float c1 = rinv[b * COUT + o] * gng[og];
            c1r[oo] = c1;
            c0r[oo] = c1 * b2[og] + gnb[og] - mu[b * COUT + o] * c1;
        }

        #pragma unroll
        for (int sweep = 0; sweep < 3; sweep++) {
            float aacc[3][4][4];
            #pragma unroll
            for (int pp = 0; pp < 3; pp++)
                #pragma unroll
                for (int oo = 0; oo < 4; oo++)
                    #pragma unroll
                    for (int i = 0; i < 4; i++) aacc[pp][oo][i] = 0.f;
            #pragma unroll 8
            for (int m = 0; m < 32; m++) {
                float4 w = *(const float4*)&sWt[m * 68 + 4 * to];
                #pragma unroll
                for (int pp = 0; pp < 3; pp++) {
                    float4 hv = *(const float4*)&sH[((sweep * 3 + pp) << 10) + (m << 5) + 4 * tq];
                    float* a0 = &aacc[pp][0][0];
                    a0[0]  = fmaf(w.x, hv.x, a0[0]);  a0[1]  = fmaf(w.x, hv.y, a0[1]);
                    a0[2]  = fmaf(w.x, hv.z, a0[2]);  a0[3]  = fmaf(w.x, hv.w, a0[3]);
                    a0[4]  = fmaf(w.y, hv.x, a0[4]);  a0[5]  = fmaf(w.y, hv.y, a0[5]);
                    a0[6]  = fmaf(w.y, hv.z, a0[6]);  a0[7]  = fmaf(w.y, hv.w, a0[7]);
                    a0[8]  = fmaf(w.z, hv.x, a0[8]);  a0[9]  = fmaf(w.z, hv.y, a0[9]);
                    a0[10] = fmaf(w.z, hv.z, a0[10]); a0[11] = fmaf(w.z, hv.w, a0[11]);
                    a0[12] = fmaf(w.w, hv.x, a0[12]); a0[13] = fmaf(w.w, hv.y, a0[13]);
                    a0[14] = fmaf(w.w, hv.z, a0[14]); a0[15] = fmaf(w.w, hv.w, a0[15]);
                }
            }
            #pragma unroll
            for (int pp = 0; pp < 3; pp++) {
                #pragma unroll
                for (int oo = 0; oo < 4; oo++) {
                    float c1 = c1r[oo], c0 = c0r[oo];
                    int ol = to * 4 + oo;
                    #pragma unroll
                    for (int i = 0; i < 4; i++) {
                        float Vv = sV[ol * 62 + (ly + sweep) * 10 + (lx0 + i + pp)];
                        float t = fmaf(c1, aacc[pp][oo][i], c0);
                        acc[oo][i] = fmaf(t, Vv, acc[oo][i]);
                    }
                }
            }
        }
    }
    #pragma unroll
    for (int oo = 0; oo < 4; oo++) {
        float4 r;
        r.x = acc[oo][0]; r.y = acc[oo][1]; r.z = acc[oo][2]; r.w = acc[oo][3];
        *(float4*)&out[((size_t)b * COUT + ob0 + to * 4 + oo) * HW + (y0 + ly) * WW + x0 + lx0] = r;
    }
}

// ---------------- launch ----------------
extern "C" void kernel_launch(void* const* d_in, const int* in_sizes, int n_in,
                              void* d_out, int out_size)
{
    const float* x     = (const float*)d_in[0];
    const float* Wk    = (const float*)d_in[1];
    const float* bn1g  = (const float*)d_in[2];
    const float* bn1b  = (const float*)d_in[3];
    const float* bn1m  = (const float*)d_in[4];
    const float* bn1v  = (const float*)d_in[5];
    const float* W1    = (const float*)d_in[6];
    const float* b1    = (const float*)d_in[7];
    const float* bn2g  = (const float*)d_in[8];
    const float* bn2b  = (const float*)d_in[9];
    const float* bn2m  = (const float*)d_in[10];
    const float* bn2v  = (const float*)d_in[11];
    const float* W2    = (const float*)d_in[12];
    const float* b2    = (const float*)d_in[13];
    const float* gng   = (const float*)d_in[14];
    const float* gnb   = (const float*)d_in[15];
    const float* Wv    = (const float*)d_in[16];
    const float* bnvg  = (const float*)d_in[17];
    const float* bnvb  = (const float*)d_in[18];
    const float* bnvm  = (const float*)d_in[19];
    const float* bnvv  = (const float*)d_in[20];
    float* out = (float*)d_out;

    float *vv, *hq, *hk, *pM, *pSh, *pmu, *pri;
    float *pWvt, *pW2t, *pbv, *pbh;
    cudaGetSymbolAddress((void**)&vv,    g_v);
    cudaGetSymbolAddress((void**)&hq,    g_hq);
    cudaGetSymbolAddress((void**)&hk,    g_hk);
    cudaGetSymbolAddress((void**)&pM,    g_M);
    cudaGetSymbolAddress((void**)&pSh,   g_Sh);
    cudaGetSymbolAddress((void**)&pmu,   g_mu);
    cudaGetSymbolAddress((void**)&pri,   g_ri);
    cudaGetSymbolAddress((void**)&pWvt,  g_Wvt);
    cudaGetSymbolAddress((void**)&pW2t,  g_W2t);
    cudaGetSymbolAddress((void**)&pbv,   g_bv);
    cudaGetSymbolAddress((void**)&pbh,   g_bh);

    static cudaStream_t s2 = nullptr;
    static cudaEvent_t evFork = nullptr, evJoin = nullptr;
    static bool init_done = false;
    if (!init_done) {
        cudaFuncSetAttribute(main_kernel,  cudaFuncAttributeMaxDynamicSharedMemorySize, 61568);
        cudaFuncSetAttribute(front_kernel, cudaFuncAttributeMaxDynamicSharedMemorySize, 57344);
        cudaStreamCreateWithFlags(&s2, cudaStreamNonBlocking);
        cudaEventCreateWithFlags(&evFork, cudaEventDisableTiming);
        cudaEventCreateWithFlags(&evJoin, cudaEventDisableTiming);
        init_done = true;
    }

    fold_kernel<<<(111392 + 255) / 256, 256>>>(Wk, bn1g, bn1b, bn1m, bn1v,
                                               W1, b1, bn2g, bn2b, bn2m, bn2v,
                                               W2, Wv, bnvg, bnvb, bnvm, bnvv);
    // fork: Wv GEMM runs on s2 concurrently with front + stats chain
    cudaEventRecord(evFork, 0);
    cudaStreamWaitEvent(s2, evFork, 0);
    pw_conv_kernel<64, false><<<dim3(49, 8, BB), 128, 0, s2>>>(x, pWvt, pbv, vv, OG);
    cudaEventRecord(evJoin, s2);

    front_kernel<<<dim3(49, BB), 256, 57344>>>(x, hq, hk);
    stats_gram_kernel<<<dim3(56, 3, BB), 256>>>(hq, hk, pbh, pM, pSh);
    stats_kernel<<<BB, 128>>>(W2, b2, pM, pSh, pmu, pri);

    // join: main needs v from s2
    cudaStreamWaitEvent(0, evJoin, 0);
    main_kernel<<<dim3(7, 14, BB * 2), 128, 61568>>>(hq, hk, vv, pW2t, b2, gng, gnb,
                                                     pmu, pri, pbh, out);
}